// round 5
// baseline (speedup 1.0000x reference)
#include <cuda_runtime.h>
#include <math.h>

// ---------------------------------------------------------------------------
// gatedGNN: x1 = relu(X@Ws1 + A@(X@Wn1) + b1)
//           r = softmax_N(x1@g1w+g1b); z = softmax_N(x1@g2w+g2b)
//           x2 = relu((x1*r)@Ws2 + A@((x1*r)@Wn2) + b2)
//              = relu(r.*(x1@Ws2) + A@(r.*(x1@Wn2)) + b2)   [row scale commutes]
//           x_enc = (1-z)*x1 + z*x2 ; out = mean(x_enc)@e2p_w + e2p_b
// ---------------------------------------------------------------------------

#define NMAX 100000
#define HID  256
#define NOUT 128

__device__ float g_act[(size_t)NMAX * HID];   // act_self + b (+ atomic act_nb)
__device__ float g_sup[(size_t)NMAX * HID];   // support = X @ W_nb
__device__ float g_x1 [(size_t)NMAX * HID];   // relu(layer1)
__device__ float g_log1[NMAX];
__device__ float g_log2[NMAX];
__device__ float g_scal[4];                   // max1, 1/sum1, max2, 1/sum2
__device__ float g_mean[HID];

// ---------------------------------------------------------------------------
// Dual-output tiled SGEMM: C[:,0:256]=A@Wself(+bias) -> g_act,
//                          C[:,0:256]=A@Wnb          -> g_sup
// grid.y: 0,1 -> Wself cols [0,128),[128,256);  2,3 -> Wnb.
// use_gate: A = g_x1, epilogue row-scale by r_i = exp(log1[i]-max1)*invsum1.
// ---------------------------------------------------------------------------
__global__ __launch_bounds__(256) void k_gemm_dual(
    const float* __restrict__ Ain,
    const float* __restrict__ Wself, const float* __restrict__ Wnb,
    const float* __restrict__ bias, int M, int use_gate)
{
    const float* A = use_gate ? g_x1 : Ain;
    __shared__ float As[16][132];   // [k][row], padded
    __shared__ float Bs[16][128];   // [k][col]

    int by = blockIdx.y;
    const float* W; float* C; int ncol0;
    if (by < 2) { W = Wself; C = g_act; ncol0 = by * 128; }
    else        { W = Wnb;   C = g_sup; ncol0 = (by - 2) * 128; }

    int tid = threadIdx.x;
    int row0 = blockIdx.x * 128;
    int tx = tid & 15, ty = tid >> 4;

    float acc[8][8];
#pragma unroll
    for (int i = 0; i < 8; i++)
#pragma unroll
        for (int j = 0; j < 8; j++) acc[i][j] = 0.f;

    for (int k0 = 0; k0 < 256; k0 += 16) {
        // A tile: 128 rows x 16 k (512 float4, 2 per thread), store transposed
#pragma unroll
        for (int l = 0; l < 2; l++) {
            int f = tid + l * 256;
            int r = f >> 2, c4 = f & 3;
            float4 v = make_float4(0.f, 0.f, 0.f, 0.f);
            int grow = row0 + r;
            if (grow < M)
                v = *(const float4*)(A + (size_t)grow * 256 + k0 + c4 * 4);
            As[c4 * 4 + 0][r] = v.x; As[c4 * 4 + 1][r] = v.y;
            As[c4 * 4 + 2][r] = v.z; As[c4 * 4 + 3][r] = v.w;
        }
        // B tile: 16 k x 128 cols (512 float4, 2 per thread)
#pragma unroll
        for (int l = 0; l < 2; l++) {
            int f = tid + l * 256;
            int r = f >> 5, c = f & 31;
            float4 v = *(const float4*)(W + (size_t)(k0 + r) * 256 + ncol0 + c * 4);
            *(float4*)&Bs[r][c * 4] = v;
        }
        __syncthreads();
#pragma unroll
        for (int kk = 0; kk < 16; kk++) {
            float ra[8], rb[8];
#pragma unroll
            for (int i = 0; i < 8; i++) ra[i] = As[kk][ty * 8 + i];
#pragma unroll
            for (int j = 0; j < 8; j++) rb[j] = Bs[kk][tx * 8 + j];
#pragma unroll
            for (int i = 0; i < 8; i++)
#pragma unroll
                for (int j = 0; j < 8; j++)
                    acc[i][j] = fmaf(ra[i], rb[j], acc[i][j]);
        }
        __syncthreads();
    }

    bool is_self = (by < 2);
#pragma unroll
    for (int i = 0; i < 8; i++) {
        int grow = row0 + ty * 8 + i;
        if (grow >= M) continue;
        float scale = 1.0f;
        if (use_gate) scale = expf(g_log1[grow] - g_scal[0]) * g_scal[1];
        float* crow = C + (size_t)grow * 256 + ncol0 + tx * 8;
#pragma unroll
        for (int j = 0; j < 8; j++) {
            float v = acc[i][j] * scale;
            if (is_self) v += bias[ncol0 + tx * 8 + j];
            crow[j] = v;
        }
    }
}

// ---------------------------------------------------------------------------
// Edge scatter: act[row] += val * sup[col]. 64 threads/edge, one float4 each,
// vector reduction (sm_90+ red.global.add.v4.f32).
// ---------------------------------------------------------------------------
__global__ __launch_bounds__(256) void k_scatter(
    const int* __restrict__ erow, const int* __restrict__ ecol,
    const float* __restrict__ evalv, int E)
{
    long long t = (long long)blockIdx.x * 256 + threadIdx.x;
    int e  = (int)(t >> 6);
    int c4 = (int)(t & 63);
    if (e >= E) return;
    int r = __ldg(&erow[e]);
    int c = __ldg(&ecol[e]);
    float v = __ldg(&evalv[e]);
    float4 m = *(const float4*)(g_sup + (size_t)c * 256 + c4 * 4);
    float* dst = g_act + (size_t)r * 256 + c4 * 4;
    asm volatile("red.global.add.v4.f32 [%0], {%1,%2,%3,%4};"
                 :: "l"(dst), "f"(m.x * v), "f"(m.y * v), "f"(m.z * v), "f"(m.w * v)
                 : "memory");
}

// ---------------------------------------------------------------------------
// x1 = relu(act); logits g1 = x1.g1w + g1b, g2 = x1.g2w + g2b. One warp/row.
// ---------------------------------------------------------------------------
__global__ __launch_bounds__(256) void k_relu_gates(
    const float* __restrict__ g1w, const float* __restrict__ g1b,
    const float* __restrict__ g2w, const float* __restrict__ g2b, int n)
{
    int row  = (blockIdx.x * blockDim.x + threadIdx.x) >> 5;
    int lane = threadIdx.x & 31;
    if (row >= n) return;
    const float4* a  = (const float4*)(g_act + (size_t)row * 256);
    float4*       xo = (float4*)(g_x1 + (size_t)row * 256);
    const float4* w1 = (const float4*)g1w;
    const float4* w2 = (const float4*)g2w;
    float d1 = 0.f, d2 = 0.f;
#pragma unroll
    for (int i = 0; i < 2; i++) {
        int idx = lane + i * 32;
        float4 v = a[idx];
        v.x = fmaxf(v.x, 0.f); v.y = fmaxf(v.y, 0.f);
        v.z = fmaxf(v.z, 0.f); v.w = fmaxf(v.w, 0.f);
        xo[idx] = v;
        float4 u = w1[idx];
        d1 += v.x * u.x + v.y * u.y + v.z * u.z + v.w * u.w;
        float4 s = w2[idx];
        d2 += v.x * s.x + v.y * s.y + v.z * s.z + v.w * s.w;
    }
    for (int o = 16; o; o >>= 1) {
        d1 += __shfl_xor_sync(0xffffffffu, d1, o);
        d2 += __shfl_xor_sync(0xffffffffu, d2, o);
    }
    if (lane == 0) { g_log1[row] = d1 + g1b[0]; g_log2[row] = d2 + g2b[0]; }
}

// ---------------------------------------------------------------------------
// Softmax stats over N logits for both gates (single block).
// ---------------------------------------------------------------------------
__global__ __launch_bounds__(1024) void k_softmax_stats(int n)
{
    __shared__ float s1[32], s2[32];
    int tid = threadIdx.x;
    int lane = tid & 31, wp = tid >> 5;

    float m1 = -3.0e38f, m2 = -3.0e38f;
    for (int i = tid; i < n; i += 1024) {
        m1 = fmaxf(m1, g_log1[i]);
        m2 = fmaxf(m2, g_log2[i]);
    }
    for (int o = 16; o; o >>= 1) {
        m1 = fmaxf(m1, __shfl_xor_sync(0xffffffffu, m1, o));
        m2 = fmaxf(m2, __shfl_xor_sync(0xffffffffu, m2, o));
    }
    if (lane == 0) { s1[wp] = m1; s2[wp] = m2; }
    __syncthreads();
    if (tid < 32) {
        m1 = s1[tid]; m2 = s2[tid];
        for (int o = 16; o; o >>= 1) {
            m1 = fmaxf(m1, __shfl_xor_sync(0xffffffffu, m1, o));
            m2 = fmaxf(m2, __shfl_xor_sync(0xffffffffu, m2, o));
        }
        if (tid == 0) { s1[0] = m1; s2[0] = m2; }
    }
    __syncthreads();
    float M1 = s1[0], M2 = s2[0];
    __syncthreads();

    float a1 = 0.f, a2 = 0.f;
    for (int i = tid; i < n; i += 1024) {
        a1 += expf(g_log1[i] - M1);
        a2 += expf(g_log2[i] - M2);
    }
    for (int o = 16; o; o >>= 1) {
        a1 += __shfl_xor_sync(0xffffffffu, a1, o);
        a2 += __shfl_xor_sync(0xffffffffu, a2, o);
    }
    if (lane == 0) { s1[wp] = a1; s2[wp] = a2; }
    __syncthreads();
    if (tid == 0) {
        float t1 = 0.f, t2 = 0.f;
        for (int w = 0; w < 32; w++) { t1 += s1[w]; t2 += s2[w]; }
        g_scal[0] = M1; g_scal[1] = 1.0f / t1;
        g_scal[2] = M2; g_scal[3] = 1.0f / t2;
    }
}

__global__ void k_zero_mean() { if (threadIdx.x < HID) g_mean[threadIdx.x] = 0.f; }

// ---------------------------------------------------------------------------
// x2 = relu(act2); x_enc = (1-z)*x1 + z*x2 -> d_out; column sums -> g_mean.
// Block: 64 rows, 256 threads; rg = thread/64 handles 16 rows of one f4 col.
// ---------------------------------------------------------------------------
__global__ __launch_bounds__(256) void k_final(float* __restrict__ out_xenc, int n)
{
    int c4 = threadIdx.x & 63;
    int rg = threadIdx.x >> 6;
    int row0 = blockIdx.x * 64 + rg * 16;
    float M2 = g_scal[2], inv2 = g_scal[3];
    float4 cs = make_float4(0.f, 0.f, 0.f, 0.f);
    for (int i = 0; i < 16; i++) {
        int row = row0 + i;
        if (row >= n) break;
        float z = expf(g_log2[row] - M2) * inv2;
        float4 a = *(const float4*)(g_act + (size_t)row * 256 + c4 * 4);
        a.x = fmaxf(a.x, 0.f); a.y = fmaxf(a.y, 0.f);
        a.z = fmaxf(a.z, 0.f); a.w = fmaxf(a.w, 0.f);
        float4 x = *(const float4*)(g_x1 + (size_t)row * 256 + c4 * 4);
        float4 e;
        e.x = x.x + z * (a.x - x.x);
        e.y = x.y + z * (a.y - x.y);
        e.z = x.z + z * (a.z - x.z);
        e.w = x.w + z * (a.w - x.w);
        *(float4*)(out_xenc + (size_t)row * 256 + c4 * 4) = e;
        cs.x += e.x; cs.y += e.y; cs.z += e.z; cs.w += e.w;
    }
    __shared__ float4 sh[4][64];
    sh[rg][c4] = cs;
    __syncthreads();
    if (rg == 0) {
        float4 t = sh[0][c4];
#pragma unroll
        for (int g = 1; g < 4; g++) {
            float4 u = sh[g][c4];
            t.x += u.x; t.y += u.y; t.z += u.z; t.w += u.w;
        }
        float* dst = g_mean + c4 * 4;
        asm volatile("red.global.add.v4.f32 [%0], {%1,%2,%3,%4};"
                     :: "l"(dst), "f"(t.x), "f"(t.y), "f"(t.z), "f"(t.w)
                     : "memory");
    }
}

// out = (colsum/N) @ e2p_w + e2p_b  (single block, 128 threads)
__global__ void k_head(const float* __restrict__ w, const float* __restrict__ b,
                       float* __restrict__ out, int n)
{
    int j = threadIdx.x;
    if (j >= NOUT) return;
    float invn = 1.0f / (float)n;
    float s = 0.f;
    for (int k = 0; k < HID; k++) s += g_mean[k] * w[k * NOUT + j];
    out[j] = s * invn + b[j];
}

// ---------------------------------------------------------------------------
extern "C" void kernel_launch(void* const* d_in, const int* in_sizes, int n_in,
                              void* d_out, int out_size)
{
    const float* inputs = (const float*)d_in[0];
    const int*   erow   = (const int*)d_in[1];
    const int*   ecol   = (const int*)d_in[2];
    const float* evalv  = (const float*)d_in[3];
    const float* Wself1 = (const float*)d_in[4];
    const float* Wnb1   = (const float*)d_in[5];
    const float* b1     = (const float*)d_in[6];
    const float* Wself2 = (const float*)d_in[7];
    const float* Wnb2   = (const float*)d_in[8];
    const float* b2     = (const float*)d_in[9];
    const float* g1w    = (const float*)d_in[10];
    const float* g1b    = (const float*)d_in[11];
    const float* g2w    = (const float*)d_in[12];
    const float* g2b    = (const float*)d_in[13];
    const float* e2pw   = (const float*)d_in[14];
    const float* e2pb   = (const float*)d_in[15];

    int N = in_sizes[0] / HID;
    int E = in_sizes[1];
    float* out = (float*)d_out;

    dim3 ggrid((N + 127) / 128, 4);
    int sc_blocks = (int)(((long long)E * 64 + 255) / 256);

    k_zero_mean<<<1, 256>>>();
    // Layer 1
    k_gemm_dual<<<ggrid, 256>>>(inputs, Wself1, Wnb1, b1, N, 0);
    k_scatter<<<sc_blocks, 256>>>(erow, ecol, evalv, E);
    k_relu_gates<<<(N + 7) / 8, 256>>>(g1w, g1b, g2w, g2b, N);
    k_softmax_stats<<<1, 1024>>>(N);
    // Layer 2 (row gate r folded into GEMM epilogue)
    k_gemm_dual<<<ggrid, 256>>>(inputs, Wself2, Wnb2, b2, N, 1);
    k_scatter<<<sc_blocks, 256>>>(erow, ecol, evalv, E);
    // Blend + mean + head
    k_final<<<(N + 63) / 64, 256>>>(out, N);
    k_head<<<1, 128>>>(e2pw, e2pb, out + (size_t)N * HID, N);
}

// round 6
// speedup vs baseline: 1.3217x; 1.3217x over previous
#include <cuda_runtime.h>
#include <math.h>

// ---------------------------------------------------------------------------
// gatedGNN: x1 = relu(X@Ws1 + A@(X@Wn1) + b1)
//           r = softmax_N(x1@g1w+g1b); z = softmax_N(x1@g2w+g2b)
//           x2 = relu(r.*(x1@Ws2) + A@(r.*(x1@Wn2)) + b2)   [row scale commutes]
//           x_enc = (1-z)*x1 + z*x2 ; out = mean(x_enc)@e2p_w + e2p_b
// GEMMs run on tensor cores: mma.sync.m16n8k8 TF32 (cvt.rna at smem fill).
// ---------------------------------------------------------------------------

#define NMAX 100000
#define HID  256
#define NOUT 128

__device__ float g_act[(size_t)NMAX * HID];   // act_self + b (+ atomic act_nb)
__device__ float g_sup[(size_t)NMAX * HID];   // support = X @ W_nb
__device__ float g_x1 [(size_t)NMAX * HID];   // relu(layer1)
__device__ float g_log1[NMAX];
__device__ float g_log2[NMAX];
__device__ float g_scal[4];                   // max1, 1/sum1, max2, 1/sum2
__device__ float g_mean[HID];

__device__ __forceinline__ unsigned f2tf32(float f) {
    unsigned u;
    asm("cvt.rna.tf32.f32 %0, %1;" : "=r"(u) : "f"(f));
    return u;
}

// ---------------------------------------------------------------------------
// Dual-output TF32 tensor-core GEMM:
//   grid.y 0,1 -> C=g_act = A@Wself (+bias), cols [0,128),[128,256)
//   grid.y 2,3 -> C=g_sup = A@Wnb
// use_gate: A = g_x1, epilogue row-scale by r_i.
// Block tile 128x128, k-chunk 32, 8 warps in 2(m) x 4(n), warp tile 64x32.
// ---------------------------------------------------------------------------
__global__ __launch_bounds__(256, 2) void k_gemm_dual(
    const float* __restrict__ Ain,
    const float* __restrict__ Wself, const float* __restrict__ Wnb,
    const float* __restrict__ bias, int M, int use_gate)
{
    const float* A = use_gate ? g_x1 : Ain;
    __shared__ unsigned As[128][36];   // [m][k], stride%32==4 -> conflict-free frags
    __shared__ unsigned Bs[32][136];   // [k][n], stride%32==8 -> conflict-free frags

    int by = blockIdx.y;
    const float* W; float* C; int ncol0;
    if (by < 2) { W = Wself; C = g_act; ncol0 = by * 128; }
    else        { W = Wnb;   C = g_sup; ncol0 = (by - 2) * 128; }

    int tid  = threadIdx.x;
    int row0 = blockIdx.x * 128;
    int wid  = tid >> 5, lane = tid & 31;
    int warp_m = wid & 1;        // 0..1 -> 64 rows each
    int warp_n = wid >> 1;       // 0..3 -> 32 cols each
    int gid = lane >> 2;         // 0..7
    int tig = lane & 3;          // 0..3

    float acc[4][4][4];
#pragma unroll
    for (int i = 0; i < 4; i++)
#pragma unroll
        for (int j = 0; j < 4; j++)
#pragma unroll
            for (int k = 0; k < 4; k++) acc[i][j][k] = 0.f;

    for (int kc = 0; kc < 256; kc += 32) {
        // A tile: 128 rows x 32 k  (1024 float4 / 256 thr = 4 each)
#pragma unroll
        for (int l = 0; l < 4; l++) {
            int idx = tid + l * 256;
            int r = idx >> 3, c4 = idx & 7;
            float4 v = make_float4(0.f, 0.f, 0.f, 0.f);
            int grow = row0 + r;
            if (grow < M)
                v = *(const float4*)(A + (size_t)grow * 256 + kc + c4 * 4);
            uint4 u; u.x = f2tf32(v.x); u.y = f2tf32(v.y);
            u.z = f2tf32(v.z); u.w = f2tf32(v.w);
            *(uint4*)&As[r][c4 * 4] = u;
        }
        // B tile: 32 k x 128 n
#pragma unroll
        for (int l = 0; l < 4; l++) {
            int idx = tid + l * 256;
            int r = idx >> 5, c4 = idx & 31;
            float4 v = *(const float4*)(W + (size_t)(kc + r) * 256 + ncol0 + c4 * 4);
            uint4 u; u.x = f2tf32(v.x); u.y = f2tf32(v.y);
            u.z = f2tf32(v.z); u.w = f2tf32(v.w);
            *(uint4*)&Bs[r][c4 * 4] = u;
        }
        __syncthreads();

#pragma unroll
        for (int ks = 0; ks < 32; ks += 8) {
            unsigned a[4][4], b[4][2];
#pragma unroll
            for (int mf = 0; mf < 4; mf++) {
                int rb = warp_m * 64 + mf * 16;
                a[mf][0] = As[rb + gid    ][ks + tig    ];
                a[mf][1] = As[rb + gid + 8][ks + tig    ];
                a[mf][2] = As[rb + gid    ][ks + tig + 4];
                a[mf][3] = As[rb + gid + 8][ks + tig + 4];
            }
#pragma unroll
            for (int nf = 0; nf < 4; nf++) {
                int cb = warp_n * 32 + nf * 8;
                b[nf][0] = Bs[ks + tig    ][cb + gid];
                b[nf][1] = Bs[ks + tig + 4][cb + gid];
            }
#pragma unroll
            for (int mf = 0; mf < 4; mf++)
#pragma unroll
                for (int nf = 0; nf < 4; nf++) {
                    asm volatile(
                        "mma.sync.aligned.m16n8k8.row.col.f32.tf32.tf32.f32 "
                        "{%0,%1,%2,%3},{%4,%5,%6,%7},{%8,%9},{%0,%1,%2,%3};"
                        : "+f"(acc[mf][nf][0]), "+f"(acc[mf][nf][1]),
                          "+f"(acc[mf][nf][2]), "+f"(acc[mf][nf][3])
                        : "r"(a[mf][0]), "r"(a[mf][1]), "r"(a[mf][2]), "r"(a[mf][3]),
                          "r"(b[nf][0]), "r"(b[nf][1]));
                }
        }
        __syncthreads();
    }

    // Epilogue: D layout c0=(gid,2*tig) c1=(gid,2*tig+1) c2=(gid+8,..) c3
    bool is_self = (by < 2);
    float mx = use_gate ? g_scal[0] : 0.f;
    float is = use_gate ? g_scal[1] : 1.f;
#pragma unroll
    for (int mf = 0; mf < 4; mf++) {
#pragma unroll
        for (int half = 0; half < 2; half++) {
            int grow = row0 + warp_m * 64 + mf * 16 + gid + half * 8;
            if (grow >= M) continue;
            float scale = use_gate ? (expf(g_log1[grow] - mx) * is) : 1.0f;
            float* crow = C + (size_t)grow * 256 + ncol0 + warp_n * 32;
#pragma unroll
            for (int nf = 0; nf < 4; nf++) {
                int col = nf * 8 + 2 * tig;
                float v0 = acc[mf][nf][half * 2 + 0] * scale;
                float v1 = acc[mf][nf][half * 2 + 1] * scale;
                if (is_self) {
                    v0 += bias[ncol0 + warp_n * 32 + col];
                    v1 += bias[ncol0 + warp_n * 32 + col + 1];
                }
                *(float2*)(crow + col) = make_float2(v0, v1);
            }
        }
    }
}

// ---------------------------------------------------------------------------
// Edge scatter: act[row] += val * sup[col]. 64 threads/edge, one float4 each,
// vector reduction (sm_90+ red.global.add.v4.f32).
// ---------------------------------------------------------------------------
__global__ __launch_bounds__(256) void k_scatter(
    const int* __restrict__ erow, const int* __restrict__ ecol,
    const float* __restrict__ evalv, int E)
{
    long long t = (long long)blockIdx.x * 256 + threadIdx.x;
    int e  = (int)(t >> 6);
    int c4 = (int)(t & 63);
    if (e >= E) return;
    int r = __ldg(&erow[e]);
    int c = __ldg(&ecol[e]);
    float v = __ldg(&evalv[e]);
    float4 m = *(const float4*)(g_sup + (size_t)c * 256 + c4 * 4);
    float* dst = g_act + (size_t)r * 256 + c4 * 4;
    asm volatile("red.global.add.v4.f32 [%0], {%1,%2,%3,%4};"
                 :: "l"(dst), "f"(m.x * v), "f"(m.y * v), "f"(m.z * v), "f"(m.w * v)
                 : "memory");
}

// ---------------------------------------------------------------------------
// x1 = relu(act); logits g1 = x1.g1w + g1b, g2 = x1.g2w + g2b. One warp/row.
// ---------------------------------------------------------------------------
__global__ __launch_bounds__(256) void k_relu_gates(
    const float* __restrict__ g1w, const float* __restrict__ g1b,
    const float* __restrict__ g2w, const float* __restrict__ g2b, int n)
{
    int row  = (blockIdx.x * blockDim.x + threadIdx.x) >> 5;
    int lane = threadIdx.x & 31;
    if (row >= n) return;
    const float4* a  = (const float4*)(g_act + (size_t)row * 256);
    float4*       xo = (float4*)(g_x1 + (size_t)row * 256);
    const float4* w1 = (const float4*)g1w;
    const float4* w2 = (const float4*)g2w;
    float d1 = 0.f, d2 = 0.f;
#pragma unroll
    for (int i = 0; i < 2; i++) {
        int idx = lane + i * 32;
        float4 v = a[idx];
        v.x = fmaxf(v.x, 0.f); v.y = fmaxf(v.y, 0.f);
        v.z = fmaxf(v.z, 0.f); v.w = fmaxf(v.w, 0.f);
        xo[idx] = v;
        float4 u = w1[idx];
        d1 += v.x * u.x + v.y * u.y + v.z * u.z + v.w * u.w;
        float4 s = w2[idx];
        d2 += v.x * s.x + v.y * s.y + v.z * s.z + v.w * s.w;
    }
    for (int o = 16; o; o >>= 1) {
        d1 += __shfl_xor_sync(0xffffffffu, d1, o);
        d2 += __shfl_xor_sync(0xffffffffu, d2, o);
    }
    if (lane == 0) { g_log1[row] = d1 + g1b[0]; g_log2[row] = d2 + g2b[0]; }
}

// ---------------------------------------------------------------------------
// Softmax stats over N logits for both gates (single block).
// ---------------------------------------------------------------------------
__global__ __launch_bounds__(1024) void k_softmax_stats(int n)
{
    __shared__ float s1[32], s2[32];
    int tid = threadIdx.x;
    int lane = tid & 31, wp = tid >> 5;

    float m1 = -3.0e38f, m2 = -3.0e38f;
    for (int i = tid; i < n; i += 1024) {
        m1 = fmaxf(m1, g_log1[i]);
        m2 = fmaxf(m2, g_log2[i]);
    }
    for (int o = 16; o; o >>= 1) {
        m1 = fmaxf(m1, __shfl_xor_sync(0xffffffffu, m1, o));
        m2 = fmaxf(m2, __shfl_xor_sync(0xffffffffu, m2, o));
    }
    if (lane == 0) { s1[wp] = m1; s2[wp] = m2; }
    __syncthreads();
    if (tid < 32) {
        m1 = s1[tid]; m2 = s2[tid];
        for (int o = 16; o; o >>= 1) {
            m1 = fmaxf(m1, __shfl_xor_sync(0xffffffffu, m1, o));
            m2 = fmaxf(m2, __shfl_xor_sync(0xffffffffu, m2, o));
        }
        if (tid == 0) { s1[0] = m1; s2[0] = m2; }
    }
    __syncthreads();
    float M1 = s1[0], M2 = s2[0];
    __syncthreads();

    float a1 = 0.f, a2 = 0.f;
    for (int i = tid; i < n; i += 1024) {
        a1 += expf(g_log1[i] - M1);
        a2 += expf(g_log2[i] - M2);
    }
    for (int o = 16; o; o >>= 1) {
        a1 += __shfl_xor_sync(0xffffffffu, a1, o);
        a2 += __shfl_xor_sync(0xffffffffu, a2, o);
    }
    if (lane == 0) { s1[wp] = a1; s2[wp] = a2; }
    __syncthreads();
    if (tid == 0) {
        float t1 = 0.f, t2 = 0.f;
        for (int w = 0; w < 32; w++) { t1 += s1[w]; t2 += s2[w]; }
        g_scal[0] = M1; g_scal[1] = 1.0f / t1;
        g_scal[2] = M2; g_scal[3] = 1.0f / t2;
    }
}

__global__ void k_zero_mean() { if (threadIdx.x < HID) g_mean[threadIdx.x] = 0.f; }

// ---------------------------------------------------------------------------
// x2 = relu(act2); x_enc = (1-z)*x1 + z*x2 -> d_out; column sums -> g_mean.
// ---------------------------------------------------------------------------
__global__ __launch_bounds__(256) void k_final(float* __restrict__ out_xenc, int n)
{
    int c4 = threadIdx.x & 63;
    int rg = threadIdx.x >> 6;
    int row0 = blockIdx.x * 64 + rg * 16;
    float M2 = g_scal[2], inv2 = g_scal[3];
    float4 cs = make_float4(0.f, 0.f, 0.f, 0.f);
    for (int i = 0; i < 16; i++) {
        int row = row0 + i;
        if (row >= n) break;
        float z = expf(g_log2[row] - M2) * inv2;
        float4 a = *(const float4*)(g_act + (size_t)row * 256 + c4 * 4);
        a.x = fmaxf(a.x, 0.f); a.y = fmaxf(a.y, 0.f);
        a.z = fmaxf(a.z, 0.f); a.w = fmaxf(a.w, 0.f);
        float4 x = *(const float4*)(g_x1 + (size_t)row * 256 + c4 * 4);
        float4 e;
        e.x = x.x + z * (a.x - x.x);
        e.y = x.y + z * (a.y - x.y);
        e.z = x.z + z * (a.z - x.z);
        e.w = x.w + z * (a.w - x.w);
        *(float4*)(out_xenc + (size_t)row * 256 + c4 * 4) = e;
        cs.x += e.x; cs.y += e.y; cs.z += e.z; cs.w += e.w;
    }
    __shared__ float4 sh[4][64];
    sh[rg][c4] = cs;
    __syncthreads();
    if (rg == 0) {
        float4 t = sh[0][c4];
#pragma unroll
        for (int g = 1; g < 4; g++) {
            float4 u = sh[g][c4];
            t.x += u.x; t.y += u.y; t.z += u.z; t.w += u.w;
        }
        float* dst = g_mean + c4 * 4;
        asm volatile("red.global.add.v4.f32 [%0], {%1,%2,%3,%4};"
                     :: "l"(dst), "f"(t.x), "f"(t.y), "f"(t.z), "f"(t.w)
                     : "memory");
    }
}

// out = (colsum/N) @ e2p_w + e2p_b  (single block, 128 threads)
__global__ void k_head(const float* __restrict__ w, const float* __restrict__ b,
                       float* __restrict__ out, int n)
{
    int j = threadIdx.x;
    if (j >= NOUT) return;
    float invn = 1.0f / (float)n;
    float s = 0.f;
    for (int k = 0; k < HID; k++) s += g_mean[k] * w[k * NOUT + j];
    out[j] = s * invn + b[j];
}

// ---------------------------------------------------------------------------
extern "C" void kernel_launch(void* const* d_in, const int* in_sizes, int n_in,
                              void* d_out, int out_size)
{
    const float* inputs = (const float*)d_in[0];
    const int*   erow   = (const int*)d_in[1];
    const int*   ecol   = (const int*)d_in[2];
    const float* evalv  = (const float*)d_in[3];
    const float* Wself1 = (const float*)d_in[4];
    const float* Wnb1   = (const float*)d_in[5];
    const float* b1     = (const float*)d_in[6];
    const float* Wself2 = (const float*)d_in[7];
    const float* Wnb2   = (const float*)d_in[8];
    const float* b2     = (const float*)d_in[9];
    const float* g1w    = (const float*)d_in[10];
    const float* g1b    = (const float*)d_in[11];
    const float* g2w    = (const float*)d_in[12];
    const float* g2b    = (const float*)d_in[13];
    const float* e2pw   = (const float*)d_in[14];
    const float* e2pb   = (const float*)d_in[15];

    int N = in_sizes[0] / HID;
    int E = in_sizes[1];
    float* out = (float*)d_out;

    dim3 ggrid((N + 127) / 128, 4);
    int sc_blocks = (int)(((long long)E * 64 + 255) / 256);

    k_zero_mean<<<1, 256>>>();
    // Layer 1
    k_gemm_dual<<<ggrid, 256>>>(inputs, Wself1, Wnb1, b1, N, 0);
    k_scatter<<<sc_blocks, 256>>>(erow, ecol, evalv, E);
    k_relu_gates<<<(N + 7) / 8, 256>>>(g1w, g1b, g2w, g2b, N);
    k_softmax_stats<<<1, 1024>>>(N);
    // Layer 2 (row gate r folded into GEMM epilogue)
    k_gemm_dual<<<ggrid, 256>>>(inputs, Wself2, Wnb2, b2, N, 1);
    k_scatter<<<sc_blocks, 256>>>(erow, ecol, evalv, E);
    // Blend + mean + head
    k_final<<<(N + 63) / 64, 256>>>(out, N);
    k_head<<<1, 128>>>(e2pw, e2pb, out + (size_t)N * HID, N);
}

// round 9
// speedup vs baseline: 1.7430x; 1.3187x over previous
#include <cuda_runtime.h>
#include <math.h>

// ---------------------------------------------------------------------------
// gatedGNN: x1 = relu(X@Ws1 + A@(X@Wn1) + b1)
//           r = softmax_N(x1@g1w+g1b); z = softmax_N(x1@g2w+g2b)
//           x2 = relu(r.*(x1@Ws2) + A@(r.*(x1@Wn2)) + b2)   [row scale commutes]
//           x_enc = (1-z)*x1 + z*x2 ; out = mean(x_enc)@e2p_w + e2p_b
// GEMMs: mma.sync.m16n8k8 TF32.  SpMM: (row, col-bucket) CSR, 4 L2-resident
// col-bucket passes, warp-per-row accumulation (no atomics in hot path).
// ---------------------------------------------------------------------------

#define NMAX 100000
#define HID  256
#define NOUT 128
#define NB   4                       // col buckets (25K cols -> 25.6MB L2 slice)
#define NKEYMAX (NMAX * NB)

__device__ float g_act[(size_t)NMAX * HID];   // act_self + b, then += act_nb
__device__ float g_sup[(size_t)NMAX * HID];   // support = X @ W_nb
__device__ float g_x1 [(size_t)NMAX * HID];   // relu(layer1)
__device__ float g_log1[NMAX];
__device__ float g_log2[NMAX];
__device__ float g_scal[4];                   // max1, 1/sum1, max2, 1/sum2
__device__ float g_mean[HID];

// CSR (built once per launch, reused by both layers)
__device__ int  g_cnt[NKEYMAX];
__device__ int  g_off[NKEYMAX + 1];
__device__ int  g_cur[NKEYMAX];
__device__ int2 g_se[3400000];                // packed (col, val_bits), E <= 3.4M

__device__ __forceinline__ unsigned f2tf32(float f) {
    unsigned u;
    asm("cvt.rna.tf32.f32 %0, %1;" : "=r"(u) : "f"(f));
    return u;
}

// ---------------------------------------------------------------------------
// CSR build
// ---------------------------------------------------------------------------
__global__ void k_zero(int nkey)
{
    int i = blockIdx.x * 256 + threadIdx.x;
    if (i < nkey) g_cnt[i] = 0;
    if (blockIdx.x == 0 && threadIdx.x < HID) g_mean[threadIdx.x] = 0.f;
}

__global__ void k_count(const int* __restrict__ erow,
                        const int* __restrict__ ecol, int E, int Q)
{
    int e = blockIdx.x * 256 + threadIdx.x;
    if (e >= E) return;
    int key = __ldg(&erow[e]) * NB + __ldg(&ecol[e]) / Q;
    atomicAdd(&g_cnt[key], 1);
}

// Single-block chunked exclusive scan over nkey counters (~400K).
__global__ __launch_bounds__(1024) void k_scan(int nkey, int E)
{
    __shared__ int s[1024];
    int tid = threadIdx.x;
    int chunk = (nkey + 1023) >> 10;
    int base = tid * chunk;
    int sum = 0;
    for (int i = 0; i < chunk; i++) {
        int idx = base + i;
        if (idx < nkey) sum += g_cnt[idx];
    }
    s[tid] = sum;
    __syncthreads();
    for (int off = 1; off < 1024; off <<= 1) {
        int t = (tid >= off) ? s[tid - off] : 0;
        __syncthreads();
        s[tid] += t;
        __syncthreads();
    }
    int run = s[tid] - sum;   // exclusive prefix of this thread's chunk
    for (int i = 0; i < chunk; i++) {
        int idx = base + i;
        if (idx < nkey) {
            int c = g_cnt[idx];
            g_off[idx] = run;
            g_cur[idx] = run;
            run += c;
        }
    }
    if (tid == 0) g_off[nkey] = E;
}

__global__ void k_fill(const int* __restrict__ erow, const int* __restrict__ ecol,
                       const float* __restrict__ evalv, int E, int Q)
{
    int e = blockIdx.x * 256 + threadIdx.x;
    if (e >= E) return;
    int c = __ldg(&ecol[e]);
    int key = __ldg(&erow[e]) * NB + c / Q;
    int pos = atomicAdd(&g_cur[key], 1);
    g_se[pos] = make_int2(c, __float_as_int(__ldg(&evalv[e])));
}

// ---------------------------------------------------------------------------
// Gather pass p: act[row] += sum_{edges of (row,p)} val * sup[col].
// Warp per row, lane covers 8 floats. No atomics; plain RMW on own row.
// ---------------------------------------------------------------------------
__global__ __launch_bounds__(256) void k_gather(int p, int n)
{
    int warp = threadIdx.x >> 5, lane = threadIdx.x & 31;
    int row = blockIdx.x * 8 + warp;
    if (row >= n) return;
    int key = row * NB + p;
    int beg = __ldg(&g_off[key]);
    int end = __ldg(&g_off[key + 1]);
    if (beg == end) return;

    float4 a0 = make_float4(0.f, 0.f, 0.f, 0.f);
    float4 a1 = make_float4(0.f, 0.f, 0.f, 0.f);
    for (int j = beg; j < end; j++) {
        int2 cv = __ldg(&g_se[j]);
        float v = __int_as_float(cv.y);
        const float* srow = g_sup + (size_t)cv.x * 256 + lane * 8;
        float4 s0 = *(const float4*)srow;
        float4 s1 = *(const float4*)(srow + 4);
        a0.x += v * s0.x; a0.y += v * s0.y; a0.z += v * s0.z; a0.w += v * s0.w;
        a1.x += v * s1.x; a1.y += v * s1.y; a1.z += v * s1.z; a1.w += v * s1.w;
    }
    float* arow = g_act + (size_t)row * 256 + lane * 8;
    float4 c0 = *(float4*)arow;
    float4 c1 = *(float4*)(arow + 4);
    c0.x += a0.x; c0.y += a0.y; c0.z += a0.z; c0.w += a0.w;
    c1.x += a1.x; c1.y += a1.y; c1.z += a1.z; c1.w += a1.w;
    *(float4*)arow = c0;
    *(float4*)(arow + 4) = c1;
}

// ---------------------------------------------------------------------------
// Dual-output TF32 tensor-core GEMM (unchanged from R5).
// ---------------------------------------------------------------------------
__global__ __launch_bounds__(256, 2) void k_gemm_dual(
    const float* __restrict__ Ain,
    const float* __restrict__ Wself, const float* __restrict__ Wnb,
    const float* __restrict__ bias, int M, int use_gate)
{
    const float* A = use_gate ? g_x1 : Ain;
    __shared__ unsigned As[128][36];
    __shared__ unsigned Bs[32][136];

    int by = blockIdx.y;
    const float* W; float* C; int ncol0;
    if (by < 2) { W = Wself; C = g_act; ncol0 = by * 128; }
    else        { W = Wnb;   C = g_sup; ncol0 = (by - 2) * 128; }

    int tid  = threadIdx.x;
    int row0 = blockIdx.x * 128;
    int wid  = tid >> 5, lane = tid & 31;
    int warp_m = wid & 1;
    int warp_n = wid >> 1;
    int gid = lane >> 2;
    int tig = lane & 3;

    float acc[4][4][4];
#pragma unroll
    for (int i = 0; i < 4; i++)
#pragma unroll
        for (int j = 0; j < 4; j++)
#pragma unroll
            for (int k = 0; k < 4; k++) acc[i][j][k] = 0.f;

    for (int kc = 0; kc < 256; kc += 32) {
#pragma unroll
        for (int l = 0; l < 4; l++) {
            int idx = tid + l * 256;
            int r = idx >> 3, c4 = idx & 7;
            float4 v = make_float4(0.f, 0.f, 0.f, 0.f);
            int grow = row0 + r;
            if (grow < M)
                v = *(const float4*)(A + (size_t)grow * 256 + kc + c4 * 4);
            uint4 u; u.x = f2tf32(v.x); u.y = f2tf32(v.y);
            u.z = f2tf32(v.z); u.w = f2tf32(v.w);
            *(uint4*)&As[r][c4 * 4] = u;
        }
#pragma unroll
        for (int l = 0; l < 4; l++) {
            int idx = tid + l * 256;
            int r = idx >> 5, c4 = idx & 31;
            float4 v = *(const float4*)(W + (size_t)(kc + r) * 256 + ncol0 + c4 * 4);
            uint4 u; u.x = f2tf32(v.x); u.y = f2tf32(v.y);
            u.z = f2tf32(v.z); u.w = f2tf32(v.w);
            *(uint4*)&Bs[r][c4 * 4] = u;
        }
        __syncthreads();

#pragma unroll
        for (int ks = 0; ks < 32; ks += 8) {
            unsigned a[4][4], b[4][2];
#pragma unroll
            for (int mf = 0; mf < 4; mf++) {
                int rb = warp_m * 64 + mf * 16;
                a[mf][0] = As[rb + gid    ][ks + tig    ];
                a[mf][1] = As[rb + gid + 8][ks + tig    ];
                a[mf][2] = As[rb + gid    ][ks + tig + 4];
                a[mf][3] = As[rb + gid + 8][ks + tig + 4];
            }
#pragma unroll
            for (int nf = 0; nf < 4; nf++) {
                int cb = warp_n * 32 + nf * 8;
                b[nf][0] = Bs[ks + tig    ][cb + gid];
                b[nf][1] = Bs[ks + tig + 4][cb + gid];
            }
#pragma unroll
            for (int mf = 0; mf < 4; mf++)
#pragma unroll
                for (int nf = 0; nf < 4; nf++) {
                    asm volatile(
                        "mma.sync.aligned.m16n8k8.row.col.f32.tf32.tf32.f32 "
                        "{%0,%1,%2,%3},{%4,%5,%6,%7},{%8,%9},{%0,%1,%2,%3};"
                        : "+f"(acc[mf][nf][0]), "+f"(acc[mf][nf][1]),
                          "+f"(acc[mf][nf][2]), "+f"(acc[mf][nf][3])
                        : "r"(a[mf][0]), "r"(a[mf][1]), "r"(a[mf][2]), "r"(a[mf][3]),
                          "r"(b[nf][0]), "r"(b[nf][1]));
                }
        }
        __syncthreads();
    }

    bool is_self = (by < 2);
    float mx = use_gate ? g_scal[0] : 0.f;
    float is = use_gate ? g_scal[1] : 1.f;
#pragma unroll
    for (int mf = 0; mf < 4; mf++) {
#pragma unroll
        for (int half = 0; half < 2; half++) {
            int grow = row0 + warp_m * 64 + mf * 16 + gid + half * 8;
            if (grow >= M) continue;
            float scale = use_gate ? (expf(g_log1[grow] - mx) * is) : 1.0f;
            float* crow = C + (size_t)grow * 256 + ncol0 + warp_n * 32;
#pragma unroll
            for (int nf = 0; nf < 4; nf++) {
                int col = nf * 8 + 2 * tig;
                float v0 = acc[mf][nf][half * 2 + 0] * scale;
                float v1 = acc[mf][nf][half * 2 + 1] * scale;
                if (is_self) {
                    v0 += bias[ncol0 + warp_n * 32 + col];
                    v1 += bias[ncol0 + warp_n * 32 + col + 1];
                }
                *(float2*)(crow + col) = make_float2(v0, v1);
            }
        }
    }
}

// ---------------------------------------------------------------------------
// x1 = relu(act); gate logits. One warp/row.
// ---------------------------------------------------------------------------
__global__ __launch_bounds__(256) void k_relu_gates(
    const float* __restrict__ g1w, const float* __restrict__ g1b,
    const float* __restrict__ g2w, const float* __restrict__ g2b, int n)
{
    int row  = (blockIdx.x * blockDim.x + threadIdx.x) >> 5;
    int lane = threadIdx.x & 31;
    if (row >= n) return;
    const float4* a  = (const float4*)(g_act + (size_t)row * 256);
    float4*       xo = (float4*)(g_x1 + (size_t)row * 256);
    const float4* w1 = (const float4*)g1w;
    const float4* w2 = (const float4*)g2w;
    float d1 = 0.f, d2 = 0.f;
#pragma unroll
    for (int i = 0; i < 2; i++) {
        int idx = lane + i * 32;
        float4 v = a[idx];
        v.x = fmaxf(v.x, 0.f); v.y = fmaxf(v.y, 0.f);
        v.z = fmaxf(v.z, 0.f); v.w = fmaxf(v.w, 0.f);
        xo[idx] = v;
        float4 u = w1[idx];
        d1 += v.x * u.x + v.y * u.y + v.z * u.z + v.w * u.w;
        float4 s = w2[idx];
        d2 += v.x * s.x + v.y * s.y + v.z * s.z + v.w * s.w;
    }
    for (int o = 16; o; o >>= 1) {
        d1 += __shfl_xor_sync(0xffffffffu, d1, o);
        d2 += __shfl_xor_sync(0xffffffffu, d2, o);
    }
    if (lane == 0) { g_log1[row] = d1 + g1b[0]; g_log2[row] = d2 + g2b[0]; }
}

// ---------------------------------------------------------------------------
// Softmax stats over N logits for both gates (single block).
// ---------------------------------------------------------------------------
__global__ __launch_bounds__(1024) void k_softmax_stats(int n)
{
    __shared__ float s1[32], s2[32];
    int tid = threadIdx.x;
    int lane = tid & 31, wp = tid >> 5;

    float m1 = -3.0e38f, m2 = -3.0e38f;
    for (int i = tid; i < n; i += 1024) {
        m1 = fmaxf(m1, g_log1[i]);
        m2 = fmaxf(m2, g_log2[i]);
    }
    for (int o = 16; o; o >>= 1) {
        m1 = fmaxf(m1, __shfl_xor_sync(0xffffffffu, m1, o));
        m2 = fmaxf(m2, __shfl_xor_sync(0xffffffffu, m2, o));
    }
    if (lane == 0) { s1[wp] = m1; s2[wp] = m2; }
    __syncthreads();
    if (tid < 32) {
        m1 = s1[tid]; m2 = s2[tid];
        for (int o = 16; o; o >>= 1) {
            m1 = fmaxf(m1, __shfl_xor_sync(0xffffffffu, m1, o));
            m2 = fmaxf(m2, __shfl_xor_sync(0xffffffffu, m2, o));
        }
        if (tid == 0) { s1[0] = m1; s2[0] = m2; }
    }
    __syncthreads();
    float M1 = s1[0], M2 = s2[0];
    __syncthreads();

    float a1 = 0.f, a2 = 0.f;
    for (int i = tid; i < n; i += 1024) {
        a1 += expf(g_log1[i] - M1);
        a2 += expf(g_log2[i] - M2);
    }
    for (int o = 16; o; o >>= 1) {
        a1 += __shfl_xor_sync(0xffffffffu, a1, o);
        a2 += __shfl_xor_sync(0xffffffffu, a2, o);
    }
    if (lane == 0) { s1[wp] = a1; s2[wp] = a2; }
    __syncthreads();
    if (tid == 0) {
        float t1 = 0.f, t2 = 0.f;
        for (int w = 0; w < 32; w++) { t1 += s1[w]; t2 += s2[w]; }
        g_scal[0] = M1; g_scal[1] = 1.0f / t1;
        g_scal[2] = M2; g_scal[3] = 1.0f / t2;
    }
}

// ---------------------------------------------------------------------------
// x2 = relu(act2); x_enc = (1-z)*x1 + z*x2 -> d_out; column sums -> g_mean.
// ---------------------------------------------------------------------------
__global__ __launch_bounds__(256) void k_final(float* __restrict__ out_xenc, int n)
{
    int c4 = threadIdx.x & 63;
    int rg = threadIdx.x >> 6;
    int row0 = blockIdx.x * 64 + rg * 16;
    float M2 = g_scal[2], inv2 = g_scal[3];
    float4 cs = make_float4(0.f, 0.f, 0.f, 0.f);
    for (int i = 0; i < 16; i++) {
        int row = row0 + i;
        if (row >= n) break;
        float z = expf(g_log2[row] - M2) * inv2;
        float4 a = *(const float4*)(g_act + (size_t)row * 256 + c4 * 4);
        a.x = fmaxf(a.x, 0.f); a.y = fmaxf(a.y, 0.f);
        a.z = fmaxf(a.z, 0.f); a.w = fmaxf(a.w, 0.f);
        float4 x = *(const float4*)(g_x1 + (size_t)row * 256 + c4 * 4);
        float4 e;
        e.x = x.x + z * (a.x - x.x);
        e.y = x.y + z * (a.y - x.y);
        e.z = x.z + z * (a.z - x.z);
        e.w = x.w + z * (a.w - x.w);
        *(float4*)(out_xenc + (size_t)row * 256 + c4 * 4) = e;
        cs.x += e.x; cs.y += e.y; cs.z += e.z; cs.w += e.w;
    }
    __shared__ float4 sh[4][64];
    sh[rg][c4] = cs;
    __syncthreads();
    if (rg == 0) {
        float4 t = sh[0][c4];
#pragma unroll
        for (int g = 1; g < 4; g++) {
            float4 u = sh[g][c4];
            t.x += u.x; t.y += u.y; t.z += u.z; t.w += u.w;
        }
        float* dst = g_mean + c4 * 4;
        asm volatile("red.global.add.v4.f32 [%0], {%1,%2,%3,%4};"
                     :: "l"(dst), "f"(t.x), "f"(t.y), "f"(t.z), "f"(t.w)
                     : "memory");
    }
}

// out = (colsum/N) @ e2p_w + e2p_b  (single block, 128 threads)
__global__ void k_head(const float* __restrict__ w, const float* __restrict__ b,
                       float* __restrict__ out, int n)
{
    int j = threadIdx.x;
    if (j >= NOUT) return;
    float invn = 1.0f / (float)n;
    float s = 0.f;
    for (int k = 0; k < HID; k++) s += g_mean[k] * w[k * NOUT + j];
    out[j] = s * invn + b[j];
}

// ---------------------------------------------------------------------------
extern "C" void kernel_launch(void* const* d_in, const int* in_sizes, int n_in,
                              void* d_out, int out_size)
{
    const float* inputs = (const float*)d_in[0];
    const int*   erow   = (const int*)d_in[1];
    const int*   ecol   = (const int*)d_in[2];
    const float* evalv  = (const float*)d_in[3];
    const float* Wself1 = (const float*)d_in[4];
    const float* Wnb1   = (const float*)d_in[5];
    const float* b1     = (const float*)d_in[6];
    const float* Wself2 = (const float*)d_in[7];
    const float* Wnb2   = (const float*)d_in[8];
    const float* b2     = (const float*)d_in[9];
    const float* g1w    = (const float*)d_in[10];
    const float* g1b    = (const float*)d_in[11];
    const float* g2w    = (const float*)d_in[12];
    const float* g2b    = (const float*)d_in[13];
    const float* e2pw   = (const float*)d_in[14];
    const float* e2pb   = (const float*)d_in[15];

    int N = in_sizes[0] / HID;
    int E = in_sizes[1];
    float* out = (float*)d_out;

    int Q = (N + NB - 1) / NB;          // cols per bucket
    int nkey = N * NB;
    dim3 ggrid((N + 127) / 128, 4);
    int eb = (E + 255) / 256;
    int gb = (N + 7) / 8;

    // CSR build (shared by both layers)
    k_zero<<<(nkey + 255) / 256, 256>>>(nkey);
    k_count<<<eb, 256>>>(erow, ecol, E, Q);
    k_scan<<<1, 1024>>>(nkey, E);
    k_fill<<<eb, 256>>>(erow, ecol, evalv, E, Q);

    // Layer 1
    k_gemm_dual<<<ggrid, 256>>>(inputs, Wself1, Wnb1, b1, N, 0);
    for (int p = 0; p < NB; p++) k_gather<<<gb, 256>>>(p, N);
    k_relu_gates<<<(N + 7) / 8, 256>>>(g1w, g1b, g2w, g2b, N);
    k_softmax_stats<<<1, 1024>>>(N);

    // Layer 2 (row gate r folded into GEMM epilogue)
    k_gemm_dual<<<ggrid, 256>>>(inputs, Wself2, Wnb2, b2, N, 1);
    for (int p = 0; p < NB; p++) k_gather<<<gb, 256>>>(p, N);

    // Blend + mean + head
    k_final<<<(N + 63) / 64, 256>>>(out, N);
    k_head<<<1, 128>>>(e2pw, e2pb, out + (size_t)N * HID, N);
}

// round 12
// speedup vs baseline: 2.3536x; 1.3504x over previous
#include <cuda_runtime.h>
#include <cuda_fp16.h>
#include <math.h>

// ---------------------------------------------------------------------------
// gatedGNN: x1 = relu(X@Ws1 + A@(X@Wn1) + b1)
//           r = softmax_N(x1@g1w+g1b); z = softmax_N(x1@g2w+g2b)
//           x2 = relu(r.*(x1@Ws2) + A@(r.*(x1@Wn2)) + b2)   [row scale commutes]
//           x_enc = (1-z)*x1 + z*x2 ; out = mean(x_enc)@e2p_w + e2p_b
// GEMMs: cp.async double-buffered TF32 mma.sync.
// sup stored fp16 (halves L2 gather bytes; 51MB -> L2-resident).
// Layer-2 sup is scaled by exp(log1-max) ONLY (fp16-normal range); the global
// 1/sum factor is applied once after the edge sum (linearity).
// Gather: warp-per-row over row-contiguous CSR, fused epilogues.
// ---------------------------------------------------------------------------

#define NMAX 100000
#define HID  256
#define NOUT 128
#define NB   4
#define NKEYMAX (NMAX * NB)
#define NMP  64                      // g_mean partial slots

__device__ float  g_act[(size_t)NMAX * HID];    // self part (+bias) fp32
__device__ __half g_suph[(size_t)NMAX * HID];   // support, fp16
__device__ float  g_x1 [(size_t)NMAX * HID];
__device__ float  g_log1[NMAX];
__device__ float  g_log2[NMAX];
__device__ float  g_scal[4];                    // max1, 1/sum1, max2, 1/sum2
__device__ float  g_meanp[NMP][HID];

__device__ int  g_cnt[NKEYMAX];
__device__ int  g_off[NKEYMAX + 1];
__device__ int  g_cur[NKEYMAX];
__device__ int2 g_se[3400000];

__device__ __forceinline__ unsigned f2tf32(float f) {
    unsigned u;
    asm("cvt.rna.tf32.f32 %0, %1;" : "=r"(u) : "f"(f));
    return u;
}
__device__ __forceinline__ void cpa16(void* smem_dst, const void* gsrc, int srcsize) {
    unsigned d = (unsigned)__cvta_generic_to_shared(smem_dst);
    asm volatile("cp.async.cg.shared.global [%0], [%1], 16, %2;"
                 :: "r"(d), "l"(gsrc), "r"(srcsize));
}

// ---------------------------------------------------------------------------
// CSR build
// ---------------------------------------------------------------------------
__global__ void k_zero(int nkey)
{
    int i = blockIdx.x * 256 + threadIdx.x;
    if (i < nkey) g_cnt[i] = 0;
    if (i < NMP * HID) ((float*)g_meanp)[i] = 0.f;
}

__global__ void k_count(const int* __restrict__ erow,
                        const int* __restrict__ ecol, int E, int Q)
{
    int e = blockIdx.x * 256 + threadIdx.x;
    if (e >= E) return;
    int key = __ldg(&erow[e]) * NB + __ldg(&ecol[e]) / Q;
    atomicAdd(&g_cnt[key], 1);
}

__global__ __launch_bounds__(1024) void k_scan(int nkey, int E)
{
    __shared__ int s[1024];
    int tid = threadIdx.x;
    int chunk = (nkey + 1023) >> 10;
    int base = tid * chunk;
    int sum = 0;
    for (int i = 0; i < chunk; i++) {
        int idx = base + i;
        if (idx < nkey) sum += g_cnt[idx];
    }
    s[tid] = sum;
    __syncthreads();
    for (int off = 1; off < 1024; off <<= 1) {
        int t = (tid >= off) ? s[tid - off] : 0;
        __syncthreads();
        s[tid] += t;
        __syncthreads();
    }
    int run = s[tid] - sum;
    for (int i = 0; i < chunk; i++) {
        int idx = base + i;
        if (idx < nkey) {
            int c = g_cnt[idx];
            g_off[idx] = run;
            g_cur[idx] = run;
            run += c;
        }
    }
    if (tid == 0) g_off[nkey] = E;
}

__global__ void k_fill(const int* __restrict__ erow, const int* __restrict__ ecol,
                       const float* __restrict__ evalv, int E, int Q)
{
    int e = blockIdx.x * 256 + threadIdx.x;
    if (e >= E) return;
    int c = __ldg(&ecol[e]);
    int key = __ldg(&erow[e]) * NB + c / Q;
    int pos = atomicAdd(&g_cur[key], 1);
    g_se[pos] = make_int2(c, __float_as_int(__ldg(&evalv[e])));
}

// ---------------------------------------------------------------------------
// cp.async double-buffered TF32 GEMM. grid.y 0,1: g_act = A@Wself+bias cols
// [0,128),[128,256). grid.y 2,3: g_suph(fp16) = A@Wnb. k-chunk 16, 2 stages.
// use_gate: self cols scaled by full r = e*invsum; nb cols scaled by e only.
// ---------------------------------------------------------------------------
__global__ __launch_bounds__(256, 2) void k_gemm_dual(
    const float* __restrict__ Ain,
    const float* __restrict__ Wself, const float* __restrict__ Wnb,
    const float* __restrict__ bias, int M, int use_gate)
{
    const float* A = use_gate ? g_x1 : Ain;
    __shared__ float As[2][128][20];
    __shared__ float Bs[2][16][136];

    int by = blockIdx.y;
    const float* W = (by < 2) ? Wself : Wnb;
    int ncol0 = (by & 1) * 128;
    bool is_self = (by < 2);

    int tid  = threadIdx.x;
    int row0 = blockIdx.x * 128;
    int wid  = tid >> 5, lane = tid & 31;
    int warp_m = wid & 1;
    int warp_n = wid >> 1;
    int gid = lane >> 2;
    int tig = lane & 3;

    float acc[4][4][4];
#pragma unroll
    for (int i = 0; i < 4; i++)
#pragma unroll
        for (int j = 0; j < 4; j++)
#pragma unroll
            for (int k = 0; k < 4; k++) acc[i][j][k] = 0.f;

    auto issue = [&](int kc, int buf) {
#pragma unroll
        for (int l = 0; l < 2; l++) {
            int idx = tid + l * 256;
            {   // A: 128 rows x 16 k
                int r = idx >> 2, c4 = idx & 3;
                int grow = row0 + r;
                cpa16(&As[buf][r][c4 * 4],
                      A + (size_t)grow * 256 + kc + c4 * 4,
                      (grow < M) ? 16 : 0);
            }
            {   // B: 16 k x 128 n
                int r = idx >> 5, c = idx & 31;
                cpa16(&Bs[buf][r][c * 4],
                      W + (size_t)(kc + r) * 256 + ncol0 + c * 4, 16);
            }
        }
        asm volatile("cp.async.commit_group;");
    };

    issue(0, 0);
    for (int ci = 0; ci < 16; ci++) {
        if (ci + 1 < 16) {
            issue((ci + 1) * 16, (ci + 1) & 1);
            asm volatile("cp.async.wait_group 1;");
        } else {
            asm volatile("cp.async.wait_group 0;");
        }
        __syncthreads();
        int buf = ci & 1;
#pragma unroll
        for (int ks = 0; ks < 16; ks += 8) {
            unsigned a[4][4], b[4][2];
#pragma unroll
            for (int mf = 0; mf < 4; mf++) {
                int rb = warp_m * 64 + mf * 16;
                a[mf][0] = f2tf32(As[buf][rb + gid    ][ks + tig    ]);
                a[mf][1] = f2tf32(As[buf][rb + gid + 8][ks + tig    ]);
                a[mf][2] = f2tf32(As[buf][rb + gid    ][ks + tig + 4]);
                a[mf][3] = f2tf32(As[buf][rb + gid + 8][ks + tig + 4]);
            }
#pragma unroll
            for (int nf = 0; nf < 4; nf++) {
                int cb = warp_n * 32 + nf * 8;
                b[nf][0] = f2tf32(Bs[buf][ks + tig    ][cb + gid]);
                b[nf][1] = f2tf32(Bs[buf][ks + tig + 4][cb + gid]);
            }
#pragma unroll
            for (int mf = 0; mf < 4; mf++)
#pragma unroll
                for (int nf = 0; nf < 4; nf++) {
                    asm volatile(
                        "mma.sync.aligned.m16n8k8.row.col.f32.tf32.tf32.f32 "
                        "{%0,%1,%2,%3},{%4,%5,%6,%7},{%8,%9},{%0,%1,%2,%3};"
                        : "+f"(acc[mf][nf][0]), "+f"(acc[mf][nf][1]),
                          "+f"(acc[mf][nf][2]), "+f"(acc[mf][nf][3])
                        : "r"(a[mf][0]), "r"(a[mf][1]), "r"(a[mf][2]), "r"(a[mf][3]),
                          "r"(b[nf][0]), "r"(b[nf][1]));
                }
        }
        __syncthreads();
    }

    float mx = use_gate ? g_scal[0] : 0.f;
    float is = use_gate ? g_scal[1] : 1.f;
#pragma unroll
    for (int mf = 0; mf < 4; mf++) {
#pragma unroll
        for (int half = 0; half < 2; half++) {
            int grow = row0 + warp_m * 64 + mf * 16 + gid + half * 8;
            if (grow >= M) continue;
            float eg = use_gate ? expf(g_log1[grow] - mx) : 1.0f;
            float scale = is_self ? (eg * is) : eg;   // nb: no invsum (fp16 range)
#pragma unroll
            for (int nf = 0; nf < 4; nf++) {
                int col = ncol0 + warp_n * 32 + nf * 8 + 2 * tig;
                float v0 = acc[mf][nf][half * 2 + 0] * scale;
                float v1 = acc[mf][nf][half * 2 + 1] * scale;
                if (is_self) {
                    v0 += bias[col];
                    v1 += bias[col + 1];
                    *(float2*)(g_act + (size_t)grow * 256 + col) = make_float2(v0, v1);
                } else {
                    *(__half2*)(g_suph + (size_t)grow * 256 + col) =
                        __floats2half2_rn(v0, v1);
                }
            }
        }
    }
}

// ---------------------------------------------------------------------------
// Edge accumulate helper: es += val * sup_fp16[col] (8 floats per lane)
// ---------------------------------------------------------------------------
__device__ __forceinline__ void acc_edge(float* es, int2 cv, int lane)
{
    float v = __int_as_float(cv.y);
    float4 raw = *(const float4*)(g_suph + (size_t)cv.x * 256 + lane * 8);
    __half2* p = (__half2*)&raw;
#pragma unroll
    for (int q = 0; q < 4; q++) {
        float2 f = __half22float2(p[q]);
        es[2 * q]     += v * f.x;
        es[2 * q + 1] += v * f.y;
    }
}

// acc = relu(self + mult * edge_sum); mult = 1 (L1) or invsum1 (L2)
__device__ __forceinline__ void gather_row(float* acc, int row, int lane, float mult)
{
    int beg = __ldg(&g_off[row * NB]);
    int end = __ldg(&g_off[(row + 1) * NB]);
    float es[8];
#pragma unroll
    for (int i = 0; i < 8; i++) es[i] = 0.f;

    int j = beg;
    for (; j + 4 <= end; j += 4) {
        int2 cv0 = __ldg(&g_se[j]);
        int2 cv1 = __ldg(&g_se[j + 1]);
        int2 cv2 = __ldg(&g_se[j + 2]);
        int2 cv3 = __ldg(&g_se[j + 3]);
        acc_edge(es, cv0, lane);
        acc_edge(es, cv1, lane);
        acc_edge(es, cv2, lane);
        acc_edge(es, cv3, lane);
    }
    for (; j < end; j++) acc_edge(es, __ldg(&g_se[j]), lane);

    const float* arow = g_act + (size_t)row * 256 + lane * 8;
    float4 c0 = *(const float4*)arow;
    float4 c1 = *(const float4*)(arow + 4);
    acc[0] = c0.x; acc[1] = c0.y; acc[2] = c0.z; acc[3] = c0.w;
    acc[4] = c1.x; acc[5] = c1.y; acc[6] = c1.z; acc[7] = c1.w;
#pragma unroll
    for (int i = 0; i < 8; i++)
        acc[i] = fmaxf(fmaf(mult, es[i], acc[i]), 0.f);
}

// ---------------------------------------------------------------------------
// Layer-1 gather fused with relu + gate logits. Warp per row.
// ---------------------------------------------------------------------------
__global__ __launch_bounds__(256) void k_gather_l1(
    const float* __restrict__ g1w, const float* __restrict__ g1b,
    const float* __restrict__ g2w, const float* __restrict__ g2b, int n)
{
    int row  = blockIdx.x * 8 + (threadIdx.x >> 5);
    int lane = threadIdx.x & 31;
    if (row >= n) return;

    float acc[8];
    gather_row(acc, row, lane, 1.0f);

    float* xrow = g_x1 + (size_t)row * 256 + lane * 8;
    *(float4*)xrow       = make_float4(acc[0], acc[1], acc[2], acc[3]);
    *(float4*)(xrow + 4) = make_float4(acc[4], acc[5], acc[6], acc[7]);

    const float* w1 = g1w + lane * 8;
    const float* w2 = g2w + lane * 8;
    float4 u0 = *(const float4*)w1, u1 = *(const float4*)(w1 + 4);
    float4 s0 = *(const float4*)w2, s1 = *(const float4*)(w2 + 4);
    float d1 = acc[0]*u0.x + acc[1]*u0.y + acc[2]*u0.z + acc[3]*u0.w
             + acc[4]*u1.x + acc[5]*u1.y + acc[6]*u1.z + acc[7]*u1.w;
    float d2 = acc[0]*s0.x + acc[1]*s0.y + acc[2]*s0.z + acc[3]*s0.w
             + acc[4]*s1.x + acc[5]*s1.y + acc[6]*s1.z + acc[7]*s1.w;
    for (int o = 16; o; o >>= 1) {
        d1 += __shfl_xor_sync(0xffffffffu, d1, o);
        d2 += __shfl_xor_sync(0xffffffffu, d2, o);
    }
    if (lane == 0) { g_log1[row] = d1 + g1b[0]; g_log2[row] = d2 + g2b[0]; }
}

// ---------------------------------------------------------------------------
// Layer-2 gather fused with relu + z-blend + x_enc store + column partials.
// ---------------------------------------------------------------------------
__global__ __launch_bounds__(256) void k_gather_l2(float* __restrict__ out_xenc, int n)
{
    __shared__ float sm[8][HID];
    int warp = threadIdx.x >> 5;
    int lane = threadIdx.x & 31;
    int row  = blockIdx.x * 8 + warp;

    float e[8];
#pragma unroll
    for (int i = 0; i < 8; i++) e[i] = 0.f;

    if (row < n) {
        float acc[8];
        gather_row(acc, row, lane, g_scal[1]);            // x2 = relu(self + invsum*Σ)
        float z = expf(g_log2[row] - g_scal[2]) * g_scal[3];
        const float* xrow = g_x1 + (size_t)row * 256 + lane * 8;
        float4 x0 = *(const float4*)xrow;
        float4 x1v = *(const float4*)(xrow + 4);
        float xs[8] = {x0.x, x0.y, x0.z, x0.w, x1v.x, x1v.y, x1v.z, x1v.w};
#pragma unroll
        for (int i = 0; i < 8; i++) e[i] = xs[i] + z * (acc[i] - xs[i]);
        float* orow = out_xenc + (size_t)row * 256 + lane * 8;
        *(float4*)orow       = make_float4(e[0], e[1], e[2], e[3]);
        *(float4*)(orow + 4) = make_float4(e[4], e[5], e[6], e[7]);
    }
#pragma unroll
    for (int i = 0; i < 8; i++) sm[warp][lane * 8 + i] = e[i];
    __syncthreads();

    int col = threadIdx.x;
    float s = 0.f;
#pragma unroll
    for (int w = 0; w < 8; w++) s += sm[w][col];
    atomicAdd(&g_meanp[blockIdx.x & (NMP - 1)][col], s);
}

// ---------------------------------------------------------------------------
// Softmax stats over N logits for both gates (single block).
// ---------------------------------------------------------------------------
__global__ __launch_bounds__(1024) void k_softmax_stats(int n)
{
    __shared__ float s1[32], s2[32];
    int tid = threadIdx.x;
    int lane = tid & 31, wp = tid >> 5;

    float m1 = -3.0e38f, m2 = -3.0e38f;
    for (int i = tid; i < n; i += 1024) {
        m1 = fmaxf(m1, g_log1[i]);
        m2 = fmaxf(m2, g_log2[i]);
    }
    for (int o = 16; o; o >>= 1) {
        m1 = fmaxf(m1, __shfl_xor_sync(0xffffffffu, m1, o));
        m2 = fmaxf(m2, __shfl_xor_sync(0xffffffffu, m2, o));
    }
    if (lane == 0) { s1[wp] = m1; s2[wp] = m2; }
    __syncthreads();
    if (tid < 32) {
        m1 = s1[tid]; m2 = s2[tid];
        for (int o = 16; o; o >>= 1) {
            m1 = fmaxf(m1, __shfl_xor_sync(0xffffffffu, m1, o));
            m2 = fmaxf(m2, __shfl_xor_sync(0xffffffffu, m2, o));
        }
        if (tid == 0) { s1[0] = m1; s2[0] = m2; }
    }
    __syncthreads();
    float M1 = s1[0], M2 = s2[0];
    __syncthreads();

    float a1 = 0.f, a2 = 0.f;
    for (int i = tid; i < n; i += 1024) {
        a1 += expf(g_log1[i] - M1);
        a2 += expf(g_log2[i] - M2);
    }
    for (int o = 16; o; o >>= 1) {
        a1 += __shfl_xor_sync(0xffffffffu, a1, o);
        a2 += __shfl_xor_sync(0xffffffffu, a2, o);
    }
    if (lane == 0) { s1[wp] = a1; s2[wp] = a2; }
    __syncthreads();
    if (tid == 0) {
        float t1 = 0.f, t2 = 0.f;
        for (int w = 0; w < 32; w++) { t1 += s1[w]; t2 += s2[w]; }
        g_scal[0] = M1; g_scal[1] = 1.0f / t1;
        g_scal[2] = M2; g_scal[3] = 1.0f / t2;
    }
}

// out = (colsum/N) @ e2p_w + e2p_b  (single block, 256 threads)
__global__ __launch_bounds__(256) void k_head(
    const float* __restrict__ w, const float* __restrict__ b,
    float* __restrict__ out, int n)
{
    __shared__ float mean[HID];
    int t = threadIdx.x;
    float s = 0.f;
#pragma unroll
    for (int p = 0; p < NMP; p++) s += g_meanp[p][t];
    mean[t] = s;
    __syncthreads();
    if (t < NOUT) {
        float invn = 1.0f / (float)n;
        float o = 0.f;
        for (int k = 0; k < HID; k++) o += mean[k] * w[k * NOUT + t];
        out[t] = o * invn + b[t];
    }
}

// ---------------------------------------------------------------------------
extern "C" void kernel_launch(void* const* d_in, const int* in_sizes, int n_in,
                              void* d_out, int out_size)
{
    const float* inputs = (const float*)d_in[0];
    const int*   erow   = (const int*)d_in[1];
    const int*   ecol   = (const int*)d_in[2];
    const float* evalv  = (const float*)d_in[3];
    const float* Wself1 = (const float*)d_in[4];
    const float* Wnb1   = (const float*)d_in[5];
    const float* b1     = (const float*)d_in[6];
    const float* Wself2 = (const float*)d_in[7];
    const float* Wnb2   = (const float*)d_in[8];
    const float* b2     = (const float*)d_in[9];
    const float* g1w    = (const float*)d_in[10];
    const float* g1b    = (const float*)d_in[11];
    const float* g2w    = (const float*)d_in[12];
    const float* g2b    = (const float*)d_in[13];
    const float* e2pw   = (const float*)d_in[14];
    const float* e2pb   = (const float*)d_in[15];

    int N = in_sizes[0] / HID;
    int E = in_sizes[1];
    float* out = (float*)d_out;

    int Q = (N + NB - 1) / NB;
    int nkey = N * NB;
    dim3 ggrid((N + 127) / 128, 4);
    int eb = (E + 255) / 256;
    int gb = (N + 7) / 8;

    // CSR build (shared by both layers)
    k_zero<<<(nkey + 255) / 256, 256>>>(nkey);
    k_count<<<eb, 256>>>(erow, ecol, E, Q);
    k_scan<<<1, 1024>>>(nkey, E);
    k_fill<<<eb, 256>>>(erow, ecol, evalv, E, Q);

    // Layer 1
    k_gemm_dual<<<ggrid, 256>>>(inputs, Wself1, Wnb1, b1, N, 0);
    k_gather_l1<<<gb, 256>>>(g1w, g1b, g2w, g2b, N);
    k_softmax_stats<<<1, 1024>>>(N);

    // Layer 2 (row gate r folded into GEMM epilogue; invsum folded into gather)
    k_gemm_dual<<<ggrid, 256>>>(inputs, Wself2, Wnb2, b2, N, 1);
    k_gather_l2<<<gb, 256>>>(out, N);

    // Head
    k_head<<<1, 256>>>(e2pw, e2pb, out + (size_t)N * HID, N);
}

// round 14
// speedup vs baseline: 3.9760x; 1.6893x over previous
#include <cuda_runtime.h>
#include <cuda_fp16.h>
#include <math.h>

// ---------------------------------------------------------------------------
// gatedGNN: x1 = relu(X@Ws1 + A@(X@Wn1) + b1)
//           r = softmax_N(x1@g1w+g1b); z = softmax_N(x1@g2w+g2b)
//           x2 = relu(r.*(x1@Ws2) + A@(r.*(x1@Wn2)) + b2)   [row scale commutes]
//           x_enc = (1-z)*x1 + z*x2 ; out = mean(x_enc)@e2p_w + e2p_b
// GEMMs: fp16 HMMA m16n8k16, cp.async double-buffered, ldmatrix frags,
//        fp32 accumulate. Inputs/W pre-converted to fp16 once.
// All __device__ scratch arrays are referenced ONLY from device code (passing
// them as kernel args from host is UB and was the R13 bug).
// sup stored fp16 (L2-resident); layer-2 sup scaled by exp(log1-max) only,
// global 1/sum applied after the edge sum (linearity; fp16 range safety).
// Gather: warp-per-row CSR (row-keyed), fused epilogues.
// ---------------------------------------------------------------------------

#define NMAX 100000
#define HID  256
#define NOUT 128
#define NMP  64

__device__ float  g_act[(size_t)NMAX * HID];    // self part (+bias) fp32
__device__ __half g_suph[(size_t)NMAX * HID];   // support, fp16
__device__ float  g_x1 [(size_t)NMAX * HID];    // x1 fp32 (blend path)
__device__ __half g_x1h[(size_t)NMAX * HID];    // x1 fp16 (L2 GEMM A)
__device__ __half g_xh [(size_t)NMAX * HID];    // inputs fp16 (L1 GEMM A)
__device__ __half g_wh [4][HID * HID];          // Ws1,Wn1,Ws2,Wn2 fp16
__device__ float  g_log1[NMAX];
__device__ float  g_log2[NMAX];
__device__ float  g_scal[4];                    // max1, 1/sum1, max2, 1/sum2
__device__ float  g_meanp[NMP][HID];

__device__ int  g_cnt[NMAX];
__device__ int  g_off[NMAX + 1];
__device__ int  g_cur[NMAX];
__device__ int2 g_se[3400000];

__device__ __forceinline__ void cpa16(void* smem_dst, const void* gsrc, int srcsize) {
    unsigned d = (unsigned)__cvta_generic_to_shared(smem_dst);
    asm volatile("cp.async.cg.shared.global [%0], [%1], 16, %2;"
                 :: "r"(d), "l"(gsrc), "r"(srcsize));
}

// ---------------------------------------------------------------------------
// fp32 -> fp16 converts (device arrays referenced internally)
// ---------------------------------------------------------------------------
__global__ void k_cvt_x(const float* __restrict__ x, int n4)
{
    int i = blockIdx.x * 256 + threadIdx.x;
    if (i >= n4) return;
    float4 v = *(const float4*)(x + (size_t)i * 4);
    __half2* d = (__half2*)(g_xh + (size_t)i * 4);
    d[0] = __floats2half2_rn(v.x, v.y);
    d[1] = __floats2half2_rn(v.z, v.w);
}

__global__ void k_cvt_w(const float* __restrict__ w0, const float* __restrict__ w1,
                        const float* __restrict__ w2, const float* __restrict__ w3)
{
    const float* src[4] = {w0, w1, w2, w3};
    const float* s = src[blockIdx.y];
    __half* o = g_wh[blockIdx.y];
    int i = blockIdx.x * 256 + threadIdx.x;   // 64 blocks * 256 = 16384 = 65536/4
    float4 v = *(const float4*)(s + (size_t)i * 4);
    __half2* d = (__half2*)(o + (size_t)i * 4);
    d[0] = __floats2half2_rn(v.x, v.y);
    d[1] = __floats2half2_rn(v.z, v.w);
}

// ---------------------------------------------------------------------------
// CSR build (row-keyed)
// ---------------------------------------------------------------------------
__global__ void k_zero(int n)
{
    int i = blockIdx.x * 256 + threadIdx.x;
    if (i < n) g_cnt[i] = 0;
    if (i < NMP * HID) ((float*)g_meanp)[i] = 0.f;
}

__global__ void k_count(const int* __restrict__ erow, int E)
{
    int e = blockIdx.x * 256 + threadIdx.x;
    if (e >= E) return;
    atomicAdd(&g_cnt[__ldg(&erow[e])], 1);
}

__global__ __launch_bounds__(1024) void k_scan(int nkey, int E)
{
    __shared__ int s[1024];
    int tid = threadIdx.x;
    int chunk = (nkey + 1023) >> 10;
    int base = tid * chunk;
    int sum = 0;
    for (int i = 0; i < chunk; i++) {
        int idx = base + i;
        if (idx < nkey) sum += g_cnt[idx];
    }
    s[tid] = sum;
    __syncthreads();
    for (int off = 1; off < 1024; off <<= 1) {
        int t = (tid >= off) ? s[tid - off] : 0;
        __syncthreads();
        s[tid] += t;
        __syncthreads();
    }
    int run = s[tid] - sum;
    for (int i = 0; i < chunk; i++) {
        int idx = base + i;
        if (idx < nkey) {
            int c = g_cnt[idx];
            g_off[idx] = run;
            g_cur[idx] = run;
            run += c;
        }
    }
    if (tid == 0) g_off[nkey] = E;
}

__global__ void k_fill(const int* __restrict__ erow, const int* __restrict__ ecol,
                       const float* __restrict__ evalv, int E)
{
    int e = blockIdx.x * 256 + threadIdx.x;
    if (e >= E) return;
    int pos = atomicAdd(&g_cur[__ldg(&erow[e])], 1);
    g_se[pos] = make_int2(__ldg(&ecol[e]), __float_as_int(__ldg(&evalv[e])));
}

// ---------------------------------------------------------------------------
// fp16 HMMA GEMM, cp.async 2-stage, k-chunk 32, ldmatrix fragments.
// layer 0: A=g_xh,  W=g_wh[0]/g_wh[1]   layer 1: A=g_x1h, W=g_wh[2]/g_wh[3]
// grid.y 0,1: g_act = A@Wself + bias, cols [0,128),[128,256)
// grid.y 2,3: g_suph = A@Wnb (fp16 out)
// layer 1: self scaled by r=e*invsum; nb scaled by e only.
// ---------------------------------------------------------------------------
__global__ __launch_bounds__(256, 2) void k_gemm_dual(
    const float* __restrict__ bias, int M, int layer)
{
    __shared__ __half As[2][128][40];   // 32k + 8 pad; row stride 80B
    __shared__ __half Bs[2][32][136];   // 128n + 8 pad; row stride 272B

    const __half* A = layer ? g_x1h : g_xh;
    int by = blockIdx.y;
    bool is_self = (by < 2);
    const __half* W = g_wh[2 * layer + (is_self ? 0 : 1)];
    int ncol0 = (by & 1) * 128;

    int tid  = threadIdx.x;
    int row0 = blockIdx.x * 128;
    int wid  = tid >> 5, lane = tid & 31;
    int warp_m = wid & 1;
    int warp_n = wid >> 1;
    int gid = lane >> 2;
    int tig = lane & 3;

    float acc[4][4][4];
#pragma unroll
    for (int i = 0; i < 4; i++)
#pragma unroll
        for (int j = 0; j < 4; j++)
#pragma unroll
            for (int k = 0; k < 4; k++) acc[i][j][k] = 0.f;

    auto issue = [&](int kc, int buf) {
#pragma unroll
        for (int l = 0; l < 2; l++) {
            int idx = tid + l * 256;
            {   // A: 128 rows x 32 halves (64B = 4 x 16B)
                int r = idx >> 2, seg = idx & 3;
                int grow = row0 + r;
                cpa16(&As[buf][r][seg * 8],
                      A + (size_t)grow * 256 + kc + seg * 8,
                      (grow < M) ? 16 : 0);
            }
            {   // B: 32 rows x 128 halves (256B = 16 x 16B)
                int k = idx >> 4, seg = idx & 15;
                cpa16(&Bs[buf][k][seg * 8],
                      W + (size_t)(kc + k) * 256 + ncol0 + seg * 8, 16);
            }
        }
        asm volatile("cp.async.commit_group;");
    };

    // ldmatrix lane-address components
    int a_lrow = (lane & 7) + ((lane >> 3) & 1) * 8;    // + rb
    int a_lk   = ((lane >> 4) & 1) * 8;                 // + ks
    int b_lrow = (lane & 7) + (((lane & 15) >> 3)) * 8; // + ks

    issue(0, 0);
    for (int ci = 0; ci < 8; ci++) {
        if (ci + 1 < 8) {
            issue((ci + 1) * 32, (ci + 1) & 1);
            asm volatile("cp.async.wait_group 1;");
        } else {
            asm volatile("cp.async.wait_group 0;");
        }
        __syncthreads();
        int buf = ci & 1;
#pragma unroll
        for (int ks = 0; ks < 32; ks += 16) {
            unsigned a[4][4], b[4][2];
#pragma unroll
            for (int mf = 0; mf < 4; mf++) {
                int rb = warp_m * 64 + mf * 16;
                unsigned ad = (unsigned)__cvta_generic_to_shared(
                    &As[buf][rb + a_lrow][ks + a_lk]);
                asm volatile(
                    "ldmatrix.sync.aligned.m8n8.x4.shared.b16 {%0,%1,%2,%3}, [%4];"
                    : "=r"(a[mf][0]), "=r"(a[mf][1]), "=r"(a[mf][2]), "=r"(a[mf][3])
                    : "r"(ad));
            }
#pragma unroll
            for (int nf = 0; nf < 4; nf++) {
                int cb = warp_n * 32 + nf * 8;
                unsigned bd = (unsigned)__cvta_generic_to_shared(
                    &Bs[buf][ks + b_lrow][cb]);
                asm volatile(
                    "ldmatrix.sync.aligned.m8n8.x2.trans.shared.b16 {%0,%1}, [%2];"
                    : "=r"(b[nf][0]), "=r"(b[nf][1])
                    : "r"(bd));
            }
#pragma unroll
            for (int mf = 0; mf < 4; mf++)
#pragma unroll
                for (int nf = 0; nf < 4; nf++) {
                    asm volatile(
                        "mma.sync.aligned.m16n8k16.row.col.f32.f16.f16.f32 "
                        "{%0,%1,%2,%3},{%4,%5,%6,%7},{%8,%9},{%0,%1,%2,%3};"
                        : "+f"(acc[mf][nf][0]), "+f"(acc[mf][nf][1]),
                          "+f"(acc[mf][nf][2]), "+f"(acc[mf][nf][3])
                        : "r"(a[mf][0]), "r"(a[mf][1]), "r"(a[mf][2]), "r"(a[mf][3]),
                          "r"(b[nf][0]), "r"(b[nf][1]));
                }
        }
        __syncthreads();
    }

    float mx = layer ? g_scal[0] : 0.f;
    float is = layer ? g_scal[1] : 1.f;
#pragma unroll
    for (int mf = 0; mf < 4; mf++) {
#pragma unroll
        for (int half = 0; half < 2; half++) {
            int grow = row0 + warp_m * 64 + mf * 16 + gid + half * 8;
            if (grow >= M) continue;
            float eg = layer ? expf(g_log1[grow] - mx) : 1.0f;
            float scale = is_self ? (eg * is) : eg;
#pragma unroll
            for (int nf = 0; nf < 4; nf++) {
                int col = ncol0 + warp_n * 32 + nf * 8 + 2 * tig;
                float v0 = acc[mf][nf][half * 2 + 0] * scale;
                float v1 = acc[mf][nf][half * 2 + 1] * scale;
                if (is_self) {
                    v0 += bias[col];
                    v1 += bias[col + 1];
                    *(float2*)(g_act + (size_t)grow * 256 + col) = make_float2(v0, v1);
                } else {
                    *(__half2*)(g_suph + (size_t)grow * 256 + col) =
                        __floats2half2_rn(v0, v1);
                }
            }
        }
    }
}

// ---------------------------------------------------------------------------
// Edge accumulate: es += val * sup_fp16[col] (8 floats per lane)
// ---------------------------------------------------------------------------
__device__ __forceinline__ void acc_edge(float* es, int2 cv, int lane)
{
    float v = __int_as_float(cv.y);
    float4 raw = *(const float4*)(g_suph + (size_t)cv.x * 256 + lane * 8);
    __half2* p = (__half2*)&raw;
#pragma unroll
    for (int q = 0; q < 4; q++) {
        float2 f = __half22float2(p[q]);
        es[2 * q]     += v * f.x;
        es[2 * q + 1] += v * f.y;
    }
}

// acc = relu(self + mult * edge_sum); mult = 1 (L1) or invsum1 (L2)
__device__ __forceinline__ void gather_row(float* acc, int row, int lane, float mult)
{
    int beg = __ldg(&g_off[row]);
    int end = __ldg(&g_off[row + 1]);
    float es[8];
#pragma unroll
    for (int i = 0; i < 8; i++) es[i] = 0.f;

    int j = beg;
    for (; j + 4 <= end; j += 4) {
        int2 cv0 = __ldg(&g_se[j]);
        int2 cv1 = __ldg(&g_se[j + 1]);
        int2 cv2 = __ldg(&g_se[j + 2]);
        int2 cv3 = __ldg(&g_se[j + 3]);
        acc_edge(es, cv0, lane);
        acc_edge(es, cv1, lane);
        acc_edge(es, cv2, lane);
        acc_edge(es, cv3, lane);
    }
    for (; j < end; j++) acc_edge(es, __ldg(&g_se[j]), lane);

    const float* arow = g_act + (size_t)row * 256 + lane * 8;
    float4 c0 = *(const float4*)arow;
    float4 c1 = *(const float4*)(arow + 4);
    acc[0] = c0.x; acc[1] = c0.y; acc[2] = c0.z; acc[3] = c0.w;
    acc[4] = c1.x; acc[5] = c1.y; acc[6] = c1.z; acc[7] = c1.w;
#pragma unroll
    for (int i = 0; i < 8; i++)
        acc[i] = fmaxf(fmaf(mult, es[i], acc[i]), 0.f);
}

// ---------------------------------------------------------------------------
// Layer-1 gather fused with relu + gate logits + fp16 x1 store. Warp per row.
// ---------------------------------------------------------------------------
__global__ __launch_bounds__(256) void k_gather_l1(
    const float* __restrict__ g1w, const float* __restrict__ g1b,
    const float* __restrict__ g2w, const float* __restrict__ g2b, int n)
{
    int row  = blockIdx.x * 8 + (threadIdx.x >> 5);
    int lane = threadIdx.x & 31;
    if (row >= n) return;

    float acc[8];
    gather_row(acc, row, lane, 1.0f);

    float* xrow = g_x1 + (size_t)row * 256 + lane * 8;
    *(float4*)xrow       = make_float4(acc[0], acc[1], acc[2], acc[3]);
    *(float4*)(xrow + 4) = make_float4(acc[4], acc[5], acc[6], acc[7]);
    __half2* xh = (__half2*)(g_x1h + (size_t)row * 256 + lane * 8);
    xh[0] = __floats2half2_rn(acc[0], acc[1]);
    xh[1] = __floats2half2_rn(acc[2], acc[3]);
    xh[2] = __floats2half2_rn(acc[4], acc[5]);
    xh[3] = __floats2half2_rn(acc[6], acc[7]);

    const float* w1 = g1w + lane * 8;
    const float* w2 = g2w + lane * 8;
    float4 u0 = *(const float4*)w1, u1 = *(const float4*)(w1 + 4);
    float4 s0 = *(const float4*)w2, s1 = *(const float4*)(w2 + 4);
    float d1 = acc[0]*u0.x + acc[1]*u0.y + acc[2]*u0.z + acc[3]*u0.w
             + acc[4]*u1.x + acc[5]*u1.y + acc[6]*u1.z + acc[7]*u1.w;
    float d2 = acc[0]*s0.x + acc[1]*s0.y + acc[2]*s0.z + acc[3]*s0.w
             + acc[4]*s1.x + acc[5]*s1.y + acc[6]*s1.z + acc[7]*s1.w;
    for (int o = 16; o; o >>= 1) {
        d1 += __shfl_xor_sync(0xffffffffu, d1, o);
        d2 += __shfl_xor_sync(0xffffffffu, d2, o);
    }
    if (lane == 0) { g_log1[row] = d1 + g1b[0]; g_log2[row] = d2 + g2b[0]; }
}

// ---------------------------------------------------------------------------
// Layer-2 gather fused with relu + z-blend + x_enc store + column partials.
// ---------------------------------------------------------------------------
__global__ __launch_bounds__(256) void k_gather_l2(float* __restrict__ out_xenc, int n)
{
    __shared__ float sm[8][HID];
    int warp = threadIdx.x >> 5;
    int lane = threadIdx.x & 31;
    int row  = blockIdx.x * 8 + warp;

    float e[8];
#pragma unroll
    for (int i = 0; i < 8; i++) e[i] = 0.f;

    if (row < n) {
        float acc[8];
        gather_row(acc, row, lane, g_scal[1]);
        float z = expf(g_log2[row] - g_scal[2]) * g_scal[3];
        const float* xrow = g_x1 + (size_t)row * 256 + lane * 8;
        float4 x0 = *(const float4*)xrow;
        float4 x1v = *(const float4*)(xrow + 4);
        float xs[8] = {x0.x, x0.y, x0.z, x0.w, x1v.x, x1v.y, x1v.z, x1v.w};
#pragma unroll
        for (int i = 0; i < 8; i++) e[i] = xs[i] + z * (acc[i] - xs[i]);
        float* orow = out_xenc + (size_t)row * 256 + lane * 8;
        *(float4*)orow       = make_float4(e[0], e[1], e[2], e[3]);
        *(float4*)(orow + 4) = make_float4(e[4], e[5], e[6], e[7]);
    }
#pragma unroll
    for (int i = 0; i < 8; i++) sm[warp][lane * 8 + i] = e[i];
    __syncthreads();

    int col = threadIdx.x;
    float s = 0.f;
#pragma unroll
    for (int w = 0; w < 8; w++) s += sm[w][col];
    atomicAdd(&g_meanp[blockIdx.x & (NMP - 1)][col], s);
}

// ---------------------------------------------------------------------------
// Softmax stats over N logits for both gates (single block).
// ---------------------------------------------------------------------------
__global__ __launch_bounds__(1024) void k_softmax_stats(int n)
{
    __shared__ float s1[32], s2[32];
    int tid = threadIdx.x;
    int lane = tid & 31, wp = tid >> 5;

    float m1 = -3.0e38f, m2 = -3.0e38f;
    for (int i = tid; i < n; i += 1024) {
        m1 = fmaxf(m1, g_log1[i]);
        m2 = fmaxf(m2, g_log2[i]);
    }
    for (int o = 16; o; o >>= 1) {
        m1 = fmaxf(m1, __shfl_xor_sync(0xffffffffu, m1, o));
        m2 = fmaxf(m2, __shfl_xor_sync(0xffffffffu, m2, o));
    }
    if (lane == 0) { s1[wp] = m1; s2[wp] = m2; }
    __syncthreads();
    if (tid < 32) {
        m1 = s1[tid]; m2 = s2[tid];
        for (int o = 16; o; o >>= 1) {
            m1 = fmaxf(m1, __shfl_xor_sync(0xffffffffu, m1, o));
            m2 = fmaxf(m2, __shfl_xor_sync(0xffffffffu, m2, o));
        }
        if (tid == 0) { s1[0] = m1; s2[0] = m2; }
    }
    __syncthreads();
    float M1 = s1[0], M2 = s2[0];
    __syncthreads();

    float a1 = 0.f, a2 = 0.f;
    for (int i = tid; i < n; i += 1024) {
        a1 += expf(g_log1[i] - M1);
        a2 += expf(g_log2[i] - M2);
    }
    for (int o = 16; o; o >>= 1) {
        a1 += __shfl_xor_sync(0xffffffffu, a1, o);
        a2 += __shfl_xor_sync(0xffffffffu, a2, o);
    }
    if (lane == 0) { s1[wp] = a1; s2[wp] = a2; }
    __syncthreads();
    if (tid == 0) {
        float t1 = 0.f, t2 = 0.f;
        for (int w = 0; w < 32; w++) { t1 += s1[w]; t2 += s2[w]; }
        g_scal[0] = M1; g_scal[1] = 1.0f / t1;
        g_scal[2] = M2; g_scal[3] = 1.0f / t2;
    }
}

// out = (colsum/N) @ e2p_w + e2p_b  (single block, 256 threads)
__global__ __launch_bounds__(256) void k_head(
    const float* __restrict__ w, const float* __restrict__ b,
    float* __restrict__ out, int n)
{
    __shared__ float mean[HID];
    int t = threadIdx.x;
    float s = 0.f;
#pragma unroll
    for (int p = 0; p < NMP; p++) s += g_meanp[p][t];
    mean[t] = s;
    __syncthreads();
    if (t < NOUT) {
        float invn = 1.0f / (float)n;
        float o = 0.f;
        for (int k = 0; k < HID; k++) o += mean[k] * w[k * NOUT + t];
        out[t] = o * invn + b[t];
    }
}

// ---------------------------------------------------------------------------
extern "C" void kernel_launch(void* const* d_in, const int* in_sizes, int n_in,
                              void* d_out, int out_size)
{
    const float* inputs = (const float*)d_in[0];
    const int*   erow   = (const int*)d_in[1];
    const int*   ecol   = (const int*)d_in[2];
    const float* evalv  = (const float*)d_in[3];
    const float* Wself1 = (const float*)d_in[4];
    const float* Wnb1   = (const float*)d_in[5];
    const float* b1     = (const float*)d_in[6];
    const float* Wself2 = (const float*)d_in[7];
    const float* Wnb2   = (const float*)d_in[8];
    const float* b2     = (const float*)d_in[9];
    const float* g1w    = (const float*)d_in[10];
    const float* g1b    = (const float*)d_in[11];
    const float* g2w    = (const float*)d_in[12];
    const float* g2b    = (const float*)d_in[13];
    const float* e2pw   = (const float*)d_in[14];
    const float* e2pb   = (const float*)d_in[15];

    int N = in_sizes[0] / HID;
    int E = in_sizes[1];
    float* out = (float*)d_out;

    dim3 ggrid((N + 127) / 128, 4);
    int eb = (E + 255) / 256;
    int gb = (N + 7) / 8;
    int n4 = (N * HID) / 4;
    int zb = (NMP * HID + 255) / 256;
    int nb = (N + 255) / 256;

    // Converts + CSR build (shared by both layers)
    k_cvt_x<<<(n4 + 255) / 256, 256>>>(inputs, n4);
    k_cvt_w<<<dim3(64, 4), 256>>>(Wself1, Wnb1, Wself2, Wnb2);
    k_zero<<<(zb > nb ? zb : nb), 256>>>(N);
    k_count<<<eb, 256>>>(erow, E);
    k_scan<<<1, 1024>>>(N, E);
    k_fill<<<eb, 256>>>(erow, ecol, evalv, E);

    // Layer 1
    k_gemm_dual<<<ggrid, 256>>>(b1, N, 0);
    k_gather_l1<<<gb, 256>>>(g1w, g1b, g2w, g2b, N);
    k_softmax_stats<<<1, 1024>>>(N);

    // Layer 2 (row gate r folded into GEMM epilogue; invsum folded into gather)
    k_gemm_dual<<<ggrid, 256>>>(b2, N, 1);
    k_gather_l2<<<gb, 256>>>(out, N);

    // Head
    k_head<<<1, 256>>>(e2pw, e2pb, out + (size_t)N * HID, N);
}

// round 16
// speedup vs baseline: 4.7274x; 1.1890x over previous
#include <cuda_runtime.h>
#include <cuda_fp16.h>
#include <math.h>

// ---------------------------------------------------------------------------
// gatedGNN: x1 = relu(X@Ws1 + A@(X@Wn1) + b1)
//           r = softmax_N(x1@g1w+g1b); z = softmax_N(x1@g2w+g2b)
//           x2 = relu(r.*(x1@Ws2) + A@(r.*(x1@Wn2)) + b2)   [row scale commutes]
//           x_enc = (1-z)*x1 + z*x2 ; out = mean(x_enc)@e2p_w + e2p_b
// GEMMs: fp16 HMMA m16n8k16, cp.async 2-stage, ldmatrix, fp32 accum.
//        Grid (4, tiles): 4 output slices of one A-tile get consecutive bids
//        -> co-resident -> A DRAM-read once, 3x L2 hits.
// CSR: 3-phase multi-block scan; count/fill at 4 edges/thread (int4 loads).
// sup fp16 (L2-resident); layer-2 sup scaled by exp(log1-max) only, 1/sum
// applied after the edge sum. Gather: warp-per-row, unroll 8, fused epilogues.
// ---------------------------------------------------------------------------

#define NMAX 100000
#define HID  256
#define NOUT 128
#define NMP  64
#define SCB  1024                     // keys per scan block

__device__ float  g_act[(size_t)NMAX * HID];    // self part (+bias) fp32
__device__ __half g_suph[(size_t)NMAX * HID];   // support, fp16
__device__ float  g_x1 [(size_t)NMAX * HID];    // x1 fp32 (blend path)
__device__ __half g_x1h[(size_t)NMAX * HID];    // x1 fp16 (L2 GEMM A)
__device__ __half g_xh [(size_t)NMAX * HID];    // inputs fp16 (L1 GEMM A)
__device__ __half g_wh [4][HID * HID];          // Ws1,Wn1,Ws2,Wn2 fp16
__device__ float  g_log1[NMAX];
__device__ float  g_log2[NMAX];
__device__ float  g_scal[4];                    // max1, 1/sum1, max2, 1/sum2
__device__ float  g_meanp[NMP][HID];

__device__ int  g_cnt[NMAX];
__device__ int  g_off[NMAX + 1];
__device__ int  g_cur[NMAX];
__device__ int  g_bsum[(NMAX + SCB - 1) / SCB];
__device__ int2 g_se[3400000];

__device__ __forceinline__ void cpa16(void* smem_dst, const void* gsrc, int srcsize) {
    unsigned d = (unsigned)__cvta_generic_to_shared(smem_dst);
    asm volatile("cp.async.cg.shared.global [%0], [%1], 16, %2;"
                 :: "r"(d), "l"(gsrc), "r"(srcsize));
}

// ---------------------------------------------------------------------------
// fp32 -> fp16 converts (device arrays referenced internally only)
// ---------------------------------------------------------------------------
__global__ void k_cvt_x(const float* __restrict__ x, int n4)
{
    int i = blockIdx.x * 256 + threadIdx.x;
    if (i >= n4) return;
    float4 v = *(const float4*)(x + (size_t)i * 4);
    __half2* d = (__half2*)(g_xh + (size_t)i * 4);
    d[0] = __floats2half2_rn(v.x, v.y);
    d[1] = __floats2half2_rn(v.z, v.w);
}

__global__ void k_cvt_w(const float* __restrict__ w0, const float* __restrict__ w1,
                        const float* __restrict__ w2, const float* __restrict__ w3)
{
    const float* src[4] = {w0, w1, w2, w3};
    const float* s = src[blockIdx.y];
    __half* o = g_wh[blockIdx.y];
    int i = blockIdx.x * 256 + threadIdx.x;
    float4 v = *(const float4*)(s + (size_t)i * 4);
    __half2* d = (__half2*)(o + (size_t)i * 4);
    d[0] = __floats2half2_rn(v.x, v.y);
    d[1] = __floats2half2_rn(v.z, v.w);
}

// ---------------------------------------------------------------------------
// CSR build (row-keyed), 4 edges/thread, multi-block scan
// ---------------------------------------------------------------------------
__global__ void k_zero(int n)
{
    int i = blockIdx.x * 256 + threadIdx.x;
    if (i < n) g_cnt[i] = 0;
    if (i < NMP * HID) ((float*)g_meanp)[i] = 0.f;
}

__global__ void k_count(const int* __restrict__ erow, int E)
{
    int base = (blockIdx.x * 256 + threadIdx.x) * 4;
    if (base + 3 < E) {
        int4 r = *(const int4*)(erow + base);
        atomicAdd(&g_cnt[r.x], 1);
        atomicAdd(&g_cnt[r.y], 1);
        atomicAdd(&g_cnt[r.z], 1);
        atomicAdd(&g_cnt[r.w], 1);
    } else {
        for (int k = 0; k < 4; k++)
            if (base + k < E) atomicAdd(&g_cnt[__ldg(&erow[base + k])], 1);
    }
}

// phase 1: intra-block exclusive scan of 1024 counts -> g_off; block sum -> g_bsum
__global__ __launch_bounds__(SCB) void k_scan1(int n)
{
    __shared__ int s[SCB];
    int tid = threadIdx.x;
    int idx = blockIdx.x * SCB + tid;
    int c = (idx < n) ? g_cnt[idx] : 0;
    s[tid] = c;
    __syncthreads();
    for (int off = 1; off < SCB; off <<= 1) {
        int t = (tid >= off) ? s[tid - off] : 0;
        __syncthreads();
        s[tid] += t;
        __syncthreads();
    }
    if (idx < n) g_off[idx] = s[tid] - c;       // exclusive within block
    if (tid == SCB - 1) g_bsum[blockIdx.x] = s[tid];
}

// phase 2: exclusive scan of block sums (tiny)
__global__ void k_scan2(int nb, int n, int E)
{
    if (threadIdx.x == 0) {
        int run = 0;
        for (int b = 0; b < nb; b++) {
            int c = g_bsum[b];
            g_bsum[b] = run;
            run += c;
        }
        g_off[n] = E;
    }
}

// phase 3: add block base; init g_cur
__global__ __launch_bounds__(SCB) void k_scan3(int n)
{
    int idx = blockIdx.x * SCB + threadIdx.x;
    if (idx >= n) return;
    int v = g_off[idx] + g_bsum[blockIdx.x];
    g_off[idx] = v;
    g_cur[idx] = v;
}

__global__ void k_fill(const int* __restrict__ erow, const int* __restrict__ ecol,
                       const float* __restrict__ evalv, int E)
{
    int base = (blockIdx.x * 256 + threadIdx.x) * 4;
    if (base + 3 < E) {
        int4 r = *(const int4*)(erow + base);
        int4 c = *(const int4*)(ecol + base);
        float4 v = *(const float4*)(evalv + base);
        int p0 = atomicAdd(&g_cur[r.x], 1);
        int p1 = atomicAdd(&g_cur[r.y], 1);
        int p2 = atomicAdd(&g_cur[r.z], 1);
        int p3 = atomicAdd(&g_cur[r.w], 1);
        g_se[p0] = make_int2(c.x, __float_as_int(v.x));
        g_se[p1] = make_int2(c.y, __float_as_int(v.y));
        g_se[p2] = make_int2(c.z, __float_as_int(v.z));
        g_se[p3] = make_int2(c.w, __float_as_int(v.w));
    } else {
        for (int k = 0; k < 4; k++) {
            int e = base + k;
            if (e >= E) break;
            int pos = atomicAdd(&g_cur[__ldg(&erow[e])], 1);
            g_se[pos] = make_int2(__ldg(&ecol[e]), __float_as_int(__ldg(&evalv[e])));
        }
    }
}

// ---------------------------------------------------------------------------
// fp16 HMMA GEMM. Grid (4, tiles): blockIdx.x = output slice, .y = A tile.
// layer 0: A=g_xh, W=g_wh[0/1];  layer 1: A=g_x1h, W=g_wh[2/3]
// slice 0,1: g_act = A@Wself + bias (cols 0-127 / 128-255)
// slice 2,3: g_suph = A@Wnb (fp16)
// layer 1: self scaled by r=e*invsum; nb scaled by e only.
// ---------------------------------------------------------------------------
__global__ __launch_bounds__(256, 2) void k_gemm_dual(
    const float* __restrict__ bias, int M, int layer)
{
    __shared__ __half As[2][128][40];   // 32k + 8 pad
    __shared__ __half Bs[2][32][136];   // 128n + 8 pad

    const __half* A = layer ? g_x1h : g_xh;
    int by = blockIdx.x;
    bool is_self = (by < 2);
    const __half* W = g_wh[2 * layer + (is_self ? 0 : 1)];
    int ncol0 = (by & 1) * 128;

    int tid  = threadIdx.x;
    int row0 = blockIdx.y * 128;
    int wid  = tid >> 5, lane = tid & 31;
    int warp_m = wid & 1;
    int warp_n = wid >> 1;
    int gid = lane >> 2;
    int tig = lane & 3;

    float acc[4][4][4];
#pragma unroll
    for (int i = 0; i < 4; i++)
#pragma unroll
        for (int j = 0; j < 4; j++)
#pragma unroll
            for (int k = 0; k < 4; k++) acc[i][j][k] = 0.f;

    auto issue = [&](int kc, int buf) {
#pragma unroll
        for (int l = 0; l < 2; l++) {
            int idx = tid + l * 256;
            {   // A: 128 rows x 32 halves
                int r = idx >> 2, seg = idx & 3;
                int grow = row0 + r;
                cpa16(&As[buf][r][seg * 8],
                      A + (size_t)grow * 256 + kc + seg * 8,
                      (grow < M) ? 16 : 0);
            }
            {   // B: 32 rows x 128 halves
                int k = idx >> 4, seg = idx & 15;
                cpa16(&Bs[buf][k][seg * 8],
                      W + (size_t)(kc + k) * 256 + ncol0 + seg * 8, 16);
            }
        }
        asm volatile("cp.async.commit_group;");
    };

    int a_lrow = (lane & 7) + ((lane >> 3) & 1) * 8;
    int a_lk   = ((lane >> 4) & 1) * 8;
    int b_lrow = (lane & 7) + (((lane & 15) >> 3)) * 8;

    issue(0, 0);
    for (int ci = 0; ci < 8; ci++) {
        if (ci + 1 < 8) {
            issue((ci + 1) * 32, (ci + 1) & 1);
            asm volatile("cp.async.wait_group 1;");
        } else {
            asm volatile("cp.async.wait_group 0;");
        }
        __syncthreads();
        int buf = ci & 1;
#pragma unroll
        for (int ks = 0; ks < 32; ks += 16) {
            unsigned a[4][4], b[4][2];
#pragma unroll
            for (int mf = 0; mf < 4; mf++) {
                int rb = warp_m * 64 + mf * 16;
                unsigned ad = (unsigned)__cvta_generic_to_shared(
                    &As[buf][rb + a_lrow][ks + a_lk]);
                asm volatile(
                    "ldmatrix.sync.aligned.m8n8.x4.shared.b16 {%0,%1,%2,%3}, [%4];"
                    : "=r"(a[mf][0]), "=r"(a[mf][1]), "=r"(a[mf][2]), "=r"(a[mf][3])
                    : "r"(ad));
            }
#pragma unroll
            for (int nf = 0; nf < 4; nf++) {
                int cb = warp_n * 32 + nf * 8;
                unsigned bd = (unsigned)__cvta_generic_to_shared(
                    &Bs[buf][ks + b_lrow][cb]);
                asm volatile(
                    "ldmatrix.sync.aligned.m8n8.x2.trans.shared.b16 {%0,%1}, [%2];"
                    : "=r"(b[nf][0]), "=r"(b[nf][1])
                    : "r"(bd));
            }
#pragma unroll
            for (int mf = 0; mf < 4; mf++)
#pragma unroll
                for (int nf = 0; nf < 4; nf++) {
                    asm volatile(
                        "mma.sync.aligned.m16n8k16.row.col.f32.f16.f16.f32 "
                        "{%0,%1,%2,%3},{%4,%5,%6,%7},{%8,%9},{%0,%1,%2,%3};"
                        : "+f"(acc[mf][nf][0]), "+f"(acc[mf][nf][1]),
                          "+f"(acc[mf][nf][2]), "+f"(acc[mf][nf][3])
                        : "r"(a[mf][0]), "r"(a[mf][1]), "r"(a[mf][2]), "r"(a[mf][3]),
                          "r"(b[nf][0]), "r"(b[nf][1]));
                }
        }
        __syncthreads();
    }

    float mx = layer ? g_scal[0] : 0.f;
    float is = layer ? g_scal[1] : 1.f;
#pragma unroll
    for (int mf = 0; mf < 4; mf++) {
#pragma unroll
        for (int half = 0; half < 2; half++) {
            int grow = row0 + warp_m * 64 + mf * 16 + gid + half * 8;
            if (grow >= M) continue;
            float eg = layer ? expf(g_log1[grow] - mx) : 1.0f;
            float scale = is_self ? (eg * is) : eg;
#pragma unroll
            for (int nf = 0; nf < 4; nf++) {
                int col = ncol0 + warp_n * 32 + nf * 8 + 2 * tig;
                float v0 = acc[mf][nf][half * 2 + 0] * scale;
                float v1 = acc[mf][nf][half * 2 + 1] * scale;
                if (is_self) {
                    v0 += bias[col];
                    v1 += bias[col + 1];
                    *(float2*)(g_act + (size_t)grow * 256 + col) = make_float2(v0, v1);
                } else {
                    *(__half2*)(g_suph + (size_t)grow * 256 + col) =
                        __floats2half2_rn(v0, v1);
                }
            }
        }
    }
}

// ---------------------------------------------------------------------------
// Edge accumulate: es += val * sup_fp16[col] (8 floats per lane)
// ---------------------------------------------------------------------------
__device__ __forceinline__ void acc_edge(float* es, int2 cv, int lane)
{
    float v = __int_as_float(cv.y);
    float4 raw = *(const float4*)(g_suph + (size_t)cv.x * 256 + lane * 8);
    __half2* p = (__half2*)&raw;
#pragma unroll
    for (int q = 0; q < 4; q++) {
        float2 f = __half22float2(p[q]);
        es[2 * q]     += v * f.x;
        es[2 * q + 1] += v * f.y;
    }
}

// acc = relu(self + mult * edge_sum); mult = 1 (L1) or invsum1 (L2)
__device__ __forceinline__ void gather_row(float* acc, int row, int lane, float mult)
{
    int beg = __ldg(&g_off[row]);
    int end = __ldg(&g_off[row + 1]);
    float es[8];
#pragma unroll
    for (int i = 0; i < 8; i++) es[i] = 0.f;

    int j = beg;
    for (; j + 8 <= end; j += 8) {
        int2 cv[8];
#pragma unroll
        for (int u = 0; u < 8; u++) cv[u] = __ldg(&g_se[j + u]);
#pragma unroll
        for (int u = 0; u < 8; u++) acc_edge(es, cv[u], lane);
    }
    for (; j < end; j++) acc_edge(es, __ldg(&g_se[j]), lane);

    const float* arow = g_act + (size_t)row * 256 + lane * 8;
    float4 c0 = *(const float4*)arow;
    float4 c1 = *(const float4*)(arow + 4);
    acc[0] = c0.x; acc[1] = c0.y; acc[2] = c0.z; acc[3] = c0.w;
    acc[4] = c1.x; acc[5] = c1.y; acc[6] = c1.z; acc[7] = c1.w;
#pragma unroll
    for (int i = 0; i < 8; i++)
        acc[i] = fmaxf(fmaf(mult, es[i], acc[i]), 0.f);
}

// ---------------------------------------------------------------------------
// Layer-1 gather fused with relu + gate logits + fp16 x1 store. Warp per row.
// ---------------------------------------------------------------------------
__global__ __launch_bounds__(256) void k_gather_l1(
    const float* __restrict__ g1w, const float* __restrict__ g1b,
    const float* __restrict__ g2w, const float* __restrict__ g2b, int n)
{
    int row  = blockIdx.x * 8 + (threadIdx.x >> 5);
    int lane = threadIdx.x & 31;
    if (row >= n) return;

    float acc[8];
    gather_row(acc, row, lane, 1.0f);

    float* xrow = g_x1 + (size_t)row * 256 + lane * 8;
    *(float4*)xrow       = make_float4(acc[0], acc[1], acc[2], acc[3]);
    *(float4*)(xrow + 4) = make_float4(acc[4], acc[5], acc[6], acc[7]);
    __half2* xh = (__half2*)(g_x1h + (size_t)row * 256 + lane * 8);
    xh[0] = __floats2half2_rn(acc[0], acc[1]);
    xh[1] = __floats2half2_rn(acc[2], acc[3]);
    xh[2] = __floats2half2_rn(acc[4], acc[5]);
    xh[3] = __floats2half2_rn(acc[6], acc[7]);

    const float* w1 = g1w + lane * 8;
    const float* w2 = g2w + lane * 8;
    float4 u0 = *(const float4*)w1, u1 = *(const float4*)(w1 + 4);
    float4 s0 = *(const float4*)w2, s1 = *(const float4*)(w2 + 4);
    float d1 = acc[0]*u0.x + acc[1]*u0.y + acc[2]*u0.z + acc[3]*u0.w
             + acc[4]*u1.x + acc[5]*u1.y + acc[6]*u1.z + acc[7]*u1.w;
    float d2 = acc[0]*s0.x + acc[1]*s0.y + acc[2]*s0.z + acc[3]*s0.w
             + acc[4]*s1.x + acc[5]*s1.y + acc[6]*s1.z + acc[7]*s1.w;
    for (int o = 16; o; o >>= 1) {
        d1 += __shfl_xor_sync(0xffffffffu, d1, o);
        d2 += __shfl_xor_sync(0xffffffffu, d2, o);
    }
    if (lane == 0) { g_log1[row] = d1 + g1b[0]; g_log2[row] = d2 + g2b[0]; }
}

// ---------------------------------------------------------------------------
// Layer-2 gather fused with relu + z-blend + x_enc store + column partials.
// ---------------------------------------------------------------------------
__global__ __launch_bounds__(256) void k_gather_l2(float* __restrict__ out_xenc, int n)
{
    __shared__ float sm[8][HID];
    int warp = threadIdx.x >> 5;
    int lane = threadIdx.x & 31;
    int row  = blockIdx.x * 8 + warp;

    float e[8];
#pragma unroll
    for (int i = 0; i < 8; i++) e[i] = 0.f;

    if (row < n) {
        float acc[8];
        gather_row(acc, row, lane, g_scal[1]);
        float z = expf(g_log2[row] - g_scal[2]) * g_scal[3];
        const float* xrow = g_x1 + (size_t)row * 256 + lane * 8;
        float4 x0 = *(const float4*)xrow;
        float4 x1v = *(const float4*)(xrow + 4);
        float xs[8] = {x0.x, x0.y, x0.z, x0.w, x1v.x, x1v.y, x1v.z, x1v.w};
#pragma unroll
        for (int i = 0; i < 8; i++) e[i] = xs[i] + z * (acc[i] - xs[i]);
        float* orow = out_xenc + (size_t)row * 256 + lane * 8;
        *(float4*)orow       = make_float4(e[0], e[1], e[2], e[3]);
        *(float4*)(orow + 4) = make_float4(e[4], e[5], e[6], e[7]);
    }
#pragma unroll
    for (int i = 0; i < 8; i++) sm[warp][lane * 8 + i] = e[i];
    __syncthreads();

    int col = threadIdx.x;
    float s = 0.f;
#pragma unroll
    for (int w = 0; w < 8; w++) s += sm[w][col];
    atomicAdd(&g_meanp[blockIdx.x & (NMP - 1)][col], s);
}

// ---------------------------------------------------------------------------
// Softmax stats over N logits for both gates (single block).
// ---------------------------------------------------------------------------
__global__ __launch_bounds__(1024) void k_softmax_stats(int n)
{
    __shared__ float s1[32], s2[32];
    int tid = threadIdx.x;
    int lane = tid & 31, wp = tid >> 5;

    float m1 = -3.0e38f, m2 = -3.0e38f;
    for (int i = tid; i < n; i += 1024) {
        m1 = fmaxf(m1, g_log1[i]);
        m2 = fmaxf(m2, g_log2[i]);
    }
    for (int o = 16; o; o >>= 1) {
        m1 = fmaxf(m1, __shfl_xor_sync(0xffffffffu, m1, o));
        m2 = fmaxf(m2, __shfl_xor_sync(0xffffffffu, m2, o));
    }
    if (lane == 0) { s1[wp] = m1; s2[wp] = m2; }
    __syncthreads();
    if (tid < 32) {
        m1 = s1[tid]; m2 = s2[tid];
        for (int o = 16; o; o >>= 1) {
            m1 = fmaxf(m1, __shfl_xor_sync(0xffffffffu, m1, o));
            m2 = fmaxf(m2, __shfl_xor_sync(0xffffffffu, m2, o));
        }
        if (tid == 0) { s1[0] = m1; s2[0] = m2; }
    }
    __syncthreads();
    float M1 = s1[0], M2 = s2[0];
    __syncthreads();

    float a1 = 0.f, a2 = 0.f;
    for (int i = tid; i < n; i += 1024) {
        a1 += expf(g_log1[i] - M1);
        a2 += expf(g_log2[i] - M2);
    }
    for (int o = 16; o; o >>= 1) {
        a1 += __shfl_xor_sync(0xffffffffu, a1, o);
        a2 += __shfl_xor_sync(0xffffffffu, a2, o);
    }
    if (lane == 0) { s1[wp] = a1; s2[wp] = a2; }
    __syncthreads();
    if (tid == 0) {
        float t1 = 0.f, t2 = 0.f;
        for (int w = 0; w < 32; w++) { t1 += s1[w]; t2 += s2[w]; }
        g_scal[0] = M1; g_scal[1] = 1.0f / t1;
        g_scal[2] = M2; g_scal[3] = 1.0f / t2;
    }
}

// out = (colsum/N) @ e2p_w + e2p_b  (single block, 256 threads)
__global__ __launch_bounds__(256) void k_head(
    const float* __restrict__ w, const float* __restrict__ b,
    float* __restrict__ out, int n)
{
    __shared__ float mean[HID];
    int t = threadIdx.x;
    float s = 0.f;
#pragma unroll
    for (int p = 0; p < NMP; p++) s += g_meanp[p][t];
    mean[t] = s;
    __syncthreads();
    if (t < NOUT) {
        float invn = 1.0f / (float)n;
        float o = 0.f;
        for (int k = 0; k < HID; k++) o += mean[k] * w[k * NOUT + t];
        out[t] = o * invn + b[t];
    }
}

// ---------------------------------------------------------------------------
extern "C" void kernel_launch(void* const* d_in, const int* in_sizes, int n_in,
                              void* d_out, int out_size)
{
    const float* inputs = (const float*)d_in[0];
    const int*   erow   = (const int*)d_in[1];
    const int*   ecol   = (const int*)d_in[2];
    const float* evalv  = (const float*)d_in[3];
    const float* Wself1 = (const float*)d_in[4];
    const float* Wnb1   = (const float*)d_in[5];
    const float* b1     = (const float*)d_in[6];
    const float* Wself2 = (const float*)d_in[7];
    const float* Wnb2   = (const float*)d_in[8];
    const float* b2     = (const float*)d_in[9];
    const float* g1w    = (const float*)d_in[10];
    const float* g1b    = (const float*)d_in[11];
    const float* g2w    = (const float*)d_in[12];
    const float* g2b    = (const float*)d_in[13];
    const float* e2pw   = (const float*)d_in[14];
    const float* e2pb   = (const float*)d_in[15];

    int N = in_sizes[0] / HID;
    int E = in_sizes[1];
    float* out = (float*)d_out;

    dim3 ggrid(4, (N + 127) / 128);             // slice-major: A-tile L2 reuse
    int eb4 = (E + 1023) / 1024;                // 4 edges/thread
    int gb = (N + 7) / 8;
    int n4 = (N * HID) / 4;
    int zb = (NMP * HID + 255) / 256;
    int nb = (N + 255) / 256;
    int sb = (N + SCB - 1) / SCB;

    // Converts + CSR build (shared by both layers)
    k_cvt_x<<<(n4 + 255) / 256, 256>>>(inputs, n4);
    k_cvt_w<<<dim3(64, 4), 256>>>(Wself1, Wnb1, Wself2, Wnb2);
    k_zero<<<(zb > nb ? zb : nb), 256>>>(N);
    k_count<<<eb4, 256>>>(erow, E);
    k_scan1<<<sb, SCB>>>(N);
    k_scan2<<<1, 32>>>(sb, N, E);
    k_scan3<<<sb, SCB>>>(N);
    k_fill<<<eb4, 256>>>(erow, ecol, evalv, E);

    // Layer 1
    k_gemm_dual<<<ggrid, 256>>>(b1, N, 0);
    k_gather_l1<<<gb, 256>>>(g1w, g1b, g2w, g2b, N);
    k_softmax_stats<<<1, 1024>>>(N);

    // Layer 2 (row gate r folded into GEMM epilogue; invsum folded into gather)
    k_gemm_dual<<<ggrid, 256>>>(b2, N, 1);
    k_gather_l2<<<gb, 256>>>(out, N);

    // Head
    k_head<<<1, 256>>>(e2pw, e2pb, out + (size_t)N * HID, N);
}

// round 17
// speedup vs baseline: 5.4430x; 1.1514x over previous
#include <cuda_runtime.h>
#include <cuda_fp16.h>
#include <math.h>

// ---------------------------------------------------------------------------
// gatedGNN: x1 = relu(X@Ws1 + A@(X@Wn1) + b1)
//           r = softmax_N(x1@g1w+g1b); z = softmax_N(x1@g2w+g2b)
//           x2 = relu(r.*(x1@Ws2) + A@(r.*(x1@Wn2)) + b2)   [row scale commutes]
//           x_enc = (1-z)*x1 + z*x2 ; out = mean(x_enc)@e2p_w + e2p_b
// GEMMs: fp16 HMMA m16n8k16, cp.async 2-stage, ldmatrix, fp32 accum.
//        Grid (4, tiles) -> A-tile L2 reuse across the 4 output slices.
// All intermediate node tensors fp16 (act/sup/x1): halves DRAM+L2 traffic;
// fp32 kept only in accumulators and the final x_enc/output path.
// CSR: 3-phase multi-block scan; count/fill at 4 edges/thread.
// Layer-2 sup scaled by exp(log1-max) only; 1/sum applied post-sum.
// Gather: warp-per-row, unroll 8, fused epilogues.
// ---------------------------------------------------------------------------

#define NMAX 100000
#define HID  256
#define NOUT 128
#define NMP  64
#define SCB  1024                     // keys per scan block

__device__ __half g_acth[(size_t)NMAX * HID];   // self part (+bias) fp16
__device__ __half g_suph[(size_t)NMAX * HID];   // support fp16
__device__ __half g_x1h[(size_t)NMAX * HID];    // x1 fp16 (GEMM A + blend)
__device__ __half g_xh [(size_t)NMAX * HID];    // inputs fp16
__device__ __half g_wh [4][HID * HID];          // Ws1,Wn1,Ws2,Wn2 fp16
__device__ float  g_log1[NMAX];
__device__ float  g_log2[NMAX];
__device__ float  g_scal[4];                    // max1, 1/sum1, max2, 1/sum2
__device__ float  g_meanp[NMP][HID];

__device__ int  g_cnt[NMAX];
__device__ int  g_off[NMAX + 1];
__device__ int  g_cur[NMAX];
__device__ int  g_bsum[(NMAX + SCB - 1) / SCB];
__device__ int2 g_se[3400000];

__device__ __forceinline__ void cpa16(void* smem_dst, const void* gsrc, int srcsize) {
    unsigned d = (unsigned)__cvta_generic_to_shared(smem_dst);
    asm volatile("cp.async.cg.shared.global [%0], [%1], 16, %2;"
                 :: "r"(d), "l"(gsrc), "r"(srcsize));
}

// load 8 contiguous halves (16B) and expand to 8 floats
__device__ __forceinline__ void ld_h8(const __half* p, float* f)
{
    float4 raw = *(const float4*)p;
    __half2* h = (__half2*)&raw;
#pragma unroll
    for (int q = 0; q < 4; q++) {
        float2 v = __half22float2(h[q]);
        f[2 * q] = v.x; f[2 * q + 1] = v.y;
    }
}

// ---------------------------------------------------------------------------
// Fused prep: x->fp16, W->fp16, zero cnt/meanp.  Block ranges:
//   [0, xb)            : convert inputs (n4 float4 chunks)
//   [xb, xb+256)       : convert 4 weight matrices (64 blocks each)
//   [xb+256, xb+256+zb): zero g_cnt (N) and g_meanp
// ---------------------------------------------------------------------------
__global__ void k_prep(const float* __restrict__ x,
                       const float* __restrict__ w0, const float* __restrict__ w1,
                       const float* __restrict__ w2, const float* __restrict__ w3,
                       int n4, int xb, int N)
{
    int bx = blockIdx.x, tid = threadIdx.x;
    if (bx < xb) {
        int i = bx * 256 + tid;
        if (i >= n4) return;
        float4 v = *(const float4*)(x + (size_t)i * 4);
        __half2* d = (__half2*)(g_xh + (size_t)i * 4);
        d[0] = __floats2half2_rn(v.x, v.y);
        d[1] = __floats2half2_rn(v.z, v.w);
    } else if (bx < xb + 256) {
        int wb = bx - xb;
        const float* src[4] = {w0, w1, w2, w3};
        const float* s = src[wb >> 6];
        __half* o = g_wh[wb >> 6];
        int i = (wb & 63) * 256 + tid;
        float4 v = *(const float4*)(s + (size_t)i * 4);
        __half2* d = (__half2*)(o + (size_t)i * 4);
        d[0] = __floats2half2_rn(v.x, v.y);
        d[1] = __floats2half2_rn(v.z, v.w);
    } else {
        int i = (bx - xb - 256) * 256 + tid;
        if (i < N) g_cnt[i] = 0;
        if (i < NMP * HID) ((float*)g_meanp)[i] = 0.f;
    }
}

// ---------------------------------------------------------------------------
// CSR build (row-keyed), 4 edges/thread, multi-block scan
// ---------------------------------------------------------------------------
__global__ void k_count(const int* __restrict__ erow, int E)
{
    int base = (blockIdx.x * 256 + threadIdx.x) * 4;
    if (base + 3 < E) {
        int4 r = *(const int4*)(erow + base);
        atomicAdd(&g_cnt[r.x], 1);
        atomicAdd(&g_cnt[r.y], 1);
        atomicAdd(&g_cnt[r.z], 1);
        atomicAdd(&g_cnt[r.w], 1);
    } else {
        for (int k = 0; k < 4; k++)
            if (base + k < E) atomicAdd(&g_cnt[__ldg(&erow[base + k])], 1);
    }
}

__global__ __launch_bounds__(SCB) void k_scan1(int n)
{
    __shared__ int s[SCB];
    int tid = threadIdx.x;
    int idx = blockIdx.x * SCB + tid;
    int c = (idx < n) ? g_cnt[idx] : 0;
    s[tid] = c;
    __syncthreads();
    for (int off = 1; off < SCB; off <<= 1) {
        int t = (tid >= off) ? s[tid - off] : 0;
        __syncthreads();
        s[tid] += t;
        __syncthreads();
    }
    if (idx < n) g_off[idx] = s[tid] - c;
    if (tid == SCB - 1) g_bsum[blockIdx.x] = s[tid];
}

__global__ void k_scan2(int nb, int n, int E)
{
    if (threadIdx.x == 0) {
        int run = 0;
        for (int b = 0; b < nb; b++) {
            int c = g_bsum[b];
            g_bsum[b] = run;
            run += c;
        }
        g_off[n] = E;
    }
}

__global__ __launch_bounds__(SCB) void k_scan3(int n)
{
    int idx = blockIdx.x * SCB + threadIdx.x;
    if (idx >= n) return;
    int v = g_off[idx] + g_bsum[blockIdx.x];
    g_off[idx] = v;
    g_cur[idx] = v;
}

__global__ void k_fill(const int* __restrict__ erow, const int* __restrict__ ecol,
                       const float* __restrict__ evalv, int E)
{
    int base = (blockIdx.x * 256 + threadIdx.x) * 4;
    if (base + 3 < E) {
        int4 r = *(const int4*)(erow + base);
        int4 c = *(const int4*)(ecol + base);
        float4 v = *(const float4*)(evalv + base);
        int p0 = atomicAdd(&g_cur[r.x], 1);
        int p1 = atomicAdd(&g_cur[r.y], 1);
        int p2 = atomicAdd(&g_cur[r.z], 1);
        int p3 = atomicAdd(&g_cur[r.w], 1);
        g_se[p0] = make_int2(c.x, __float_as_int(v.x));
        g_se[p1] = make_int2(c.y, __float_as_int(v.y));
        g_se[p2] = make_int2(c.z, __float_as_int(v.z));
        g_se[p3] = make_int2(c.w, __float_as_int(v.w));
    } else {
        for (int k = 0; k < 4; k++) {
            int e = base + k;
            if (e >= E) break;
            int pos = atomicAdd(&g_cur[__ldg(&erow[e])], 1);
            g_se[pos] = make_int2(__ldg(&ecol[e]), __float_as_int(__ldg(&evalv[e])));
        }
    }
}

// ---------------------------------------------------------------------------
// fp16 HMMA GEMM. Grid (4, tiles): blockIdx.x = output slice, .y = A tile.
// layer 0: A=g_xh, W=g_wh[0/1];  layer 1: A=g_x1h, W=g_wh[2/3]
// slice 0,1: g_acth = A@Wself + bias (fp16, cols 0-127 / 128-255)
// slice 2,3: g_suph = A@Wnb (fp16)
// layer 1: self scaled by r=e*invsum; nb scaled by e only.
// ---------------------------------------------------------------------------
__global__ __launch_bounds__(256, 2) void k_gemm_dual(
    const float* __restrict__ bias, int M, int layer)
{
    __shared__ __half As[2][128][40];   // 32k + 8 pad
    __shared__ __half Bs[2][32][136];   // 128n + 8 pad

    const __half* A = layer ? g_x1h : g_xh;
    int by = blockIdx.x;
    bool is_self = (by < 2);
    const __half* W = g_wh[2 * layer + (is_self ? 0 : 1)];
    int ncol0 = (by & 1) * 128;

    int tid  = threadIdx.x;
    int row0 = blockIdx.y * 128;
    int wid  = tid >> 5, lane = tid & 31;
    int warp_m = wid & 1;
    int warp_n = wid >> 1;
    int gid = lane >> 2;
    int tig = lane & 3;

    float acc[4][4][4];
#pragma unroll
    for (int i = 0; i < 4; i++)
#pragma unroll
        for (int j = 0; j < 4; j++)
#pragma unroll
            for (int k = 0; k < 4; k++) acc[i][j][k] = 0.f;

    auto issue = [&](int kc, int buf) {
#pragma unroll
        for (int l = 0; l < 2; l++) {
            int idx = tid + l * 256;
            {
                int r = idx >> 2, seg = idx & 3;
                int grow = row0 + r;
                cpa16(&As[buf][r][seg * 8],
                      A + (size_t)grow * 256 + kc + seg * 8,
                      (grow < M) ? 16 : 0);
            }
            {
                int k = idx >> 4, seg = idx & 15;
                cpa16(&Bs[buf][k][seg * 8],
                      W + (size_t)(kc + k) * 256 + ncol0 + seg * 8, 16);
            }
        }
        asm volatile("cp.async.commit_group;");
    };

    int a_lrow = (lane & 7) + ((lane >> 3) & 1) * 8;
    int a_lk   = ((lane >> 4) & 1) * 8;
    int b_lrow = (lane & 7) + (((lane & 15) >> 3)) * 8;

    issue(0, 0);
    for (int ci = 0; ci < 8; ci++) {
        if (ci + 1 < 8) {
            issue((ci + 1) * 32, (ci + 1) & 1);
            asm volatile("cp.async.wait_group 1;");
        } else {
            asm volatile("cp.async.wait_group 0;");
        }
        __syncthreads();
        int buf = ci & 1;
#pragma unroll
        for (int ks = 0; ks < 32; ks += 16) {
            unsigned a[4][4], b[4][2];
#pragma unroll
            for (int mf = 0; mf < 4; mf++) {
                int rb = warp_m * 64 + mf * 16;
                unsigned ad = (unsigned)__cvta_generic_to_shared(
                    &As[buf][rb + a_lrow][ks + a_lk]);
                asm volatile(
                    "ldmatrix.sync.aligned.m8n8.x4.shared.b16 {%0,%1,%2,%3}, [%4];"
                    : "=r"(a[mf][0]), "=r"(a[mf][1]), "=r"(a[mf][2]), "=r"(a[mf][3])
                    : "r"(ad));
            }
#pragma unroll
            for (int nf = 0; nf < 4; nf++) {
                int cb = warp_n * 32 + nf * 8;
                unsigned bd = (unsigned)__cvta_generic_to_shared(
                    &Bs[buf][ks + b_lrow][cb]);
                asm volatile(
                    "ldmatrix.sync.aligned.m8n8.x2.trans.shared.b16 {%0,%1}, [%2];"
                    : "=r"(b[nf][0]), "=r"(b[nf][1])
                    : "r"(bd));
            }
#pragma unroll
            for (int mf = 0; mf < 4; mf++)
#pragma unroll
                for (int nf = 0; nf < 4; nf++) {
                    asm volatile(
                        "mma.sync.aligned.m16n8k16.row.col.f32.f16.f16.f32 "
                        "{%0,%1,%2,%3},{%4,%5,%6,%7},{%8,%9},{%0,%1,%2,%3};"
                        : "+f"(acc[mf][nf][0]), "+f"(acc[mf][nf][1]),
                          "+f"(acc[mf][nf][2]), "+f"(acc[mf][nf][3])
                        : "r"(a[mf][0]), "r"(a[mf][1]), "r"(a[mf][2]), "r"(a[mf][3]),
                          "r"(b[nf][0]), "r"(b[nf][1]));
                }
        }
        __syncthreads();
    }

    float mx = layer ? g_scal[0] : 0.f;
    float is = layer ? g_scal[1] : 1.f;
#pragma unroll
    for (int mf = 0; mf < 4; mf++) {
#pragma unroll
        for (int half = 0; half < 2; half++) {
            int grow = row0 + warp_m * 64 + mf * 16 + gid + half * 8;
            if (grow >= M) continue;
            float eg = layer ? expf(g_log1[grow] - mx) : 1.0f;
            float scale = is_self ? (eg * is) : eg;
#pragma unroll
            for (int nf = 0; nf < 4; nf++) {
                int col = ncol0 + warp_n * 32 + nf * 8 + 2 * tig;
                float v0 = acc[mf][nf][half * 2 + 0] * scale;
                float v1 = acc[mf][nf][half * 2 + 1] * scale;
                if (is_self) {
                    v0 += bias[col];
                    v1 += bias[col + 1];
                    *(__half2*)(g_acth + (size_t)grow * 256 + col) =
                        __floats2half2_rn(v0, v1);
                } else {
                    *(__half2*)(g_suph + (size_t)grow * 256 + col) =
                        __floats2half2_rn(v0, v1);
                }
            }
        }
    }
}

// ---------------------------------------------------------------------------
// Edge accumulate: es += val * sup_fp16[col] (8 floats per lane)
// ---------------------------------------------------------------------------
__device__ __forceinline__ void acc_edge(float* es, int2 cv, int lane)
{
    float v = __int_as_float(cv.y);
    float f[8];
    ld_h8(g_suph + (size_t)cv.x * 256 + lane * 8, f);
#pragma unroll
    for (int q = 0; q < 8; q++) es[q] += v * f[q];
}

// acc = relu(self + mult * edge_sum); mult = 1 (L1) or invsum1 (L2)
__device__ __forceinline__ void gather_row(float* acc, int row, int lane, float mult)
{
    int beg = __ldg(&g_off[row]);
    int end = __ldg(&g_off[row + 1]);
    float es[8];
#pragma unroll
    for (int i = 0; i < 8; i++) es[i] = 0.f;

    int j = beg;
    for (; j + 8 <= end; j += 8) {
        int2 cv[8];
#pragma unroll
        for (int u = 0; u < 8; u++) cv[u] = __ldg(&g_se[j + u]);
#pragma unroll
        for (int u = 0; u < 8; u++) acc_edge(es, cv[u], lane);
    }
    for (; j < end; j++) acc_edge(es, __ldg(&g_se[j]), lane);

    float self[8];
    ld_h8(g_acth + (size_t)row * 256 + lane * 8, self);
#pragma unroll
    for (int i = 0; i < 8; i++)
        acc[i] = fmaxf(fmaf(mult, es[i], self[i]), 0.f);
}

// ---------------------------------------------------------------------------
// Layer-1 gather fused with relu + gate logits + fp16 x1 store. Warp per row.
// ---------------------------------------------------------------------------
__global__ __launch_bounds__(256) void k_gather_l1(
    const float* __restrict__ g1w, const float* __restrict__ g1b,
    const float* __restrict__ g2w, const float* __restrict__ g2b, int n)
{
    int row  = blockIdx.x * 8 + (threadIdx.x >> 5);
    int lane = threadIdx.x & 31;
    if (row >= n) return;

    float acc[8];
    gather_row(acc, row, lane, 1.0f);

    __half2* xh = (__half2*)(g_x1h + (size_t)row * 256 + lane * 8);
    xh[0] = __floats2half2_rn(acc[0], acc[1]);
    xh[1] = __floats2half2_rn(acc[2], acc[3]);
    xh[2] = __floats2half2_rn(acc[4], acc[5]);
    xh[3] = __floats2half2_rn(acc[6], acc[7]);

    const float* w1 = g1w + lane * 8;
    const float* w2 = g2w + lane * 8;
    float4 u0 = *(const float4*)w1, u1 = *(const float4*)(w1 + 4);
    float4 s0 = *(const float4*)w2, s1 = *(const float4*)(w2 + 4);
    float d1 = acc[0]*u0.x + acc[1]*u0.y + acc[2]*u0.z + acc[3]*u0.w
             + acc[4]*u1.x + acc[5]*u1.y + acc[6]*u1.z + acc[7]*u1.w;
    float d2 = acc[0]*s0.x + acc[1]*s0.y + acc[2]*s0.z + acc[3]*s0.w
             + acc[4]*s1.x + acc[5]*s1.y + acc[6]*s1.z + acc[7]*s1.w;
    for (int o = 16; o; o >>= 1) {
        d1 += __shfl_xor_sync(0xffffffffu, d1, o);
        d2 += __shfl_xor_sync(0xffffffffu, d2, o);
    }
    if (lane == 0) { g_log1[row] = d1 + g1b[0]; g_log2[row] = d2 + g2b[0]; }
}

// ---------------------------------------------------------------------------
// Layer-2 gather fused with relu + z-blend + x_enc store + column partials.
// ---------------------------------------------------------------------------
__global__ __launch_bounds__(256) void k_gather_l2(float* __restrict__ out_xenc, int n)
{
    __shared__ float sm[8][HID];
    int warp = threadIdx.x >> 5;
    int lane = threadIdx.x & 31;
    int row  = blockIdx.x * 8 + warp;

    float e[8];
#pragma unroll
    for (int i = 0; i < 8; i++) e[i] = 0.f;

    if (row < n) {
        float acc[8];
        gather_row(acc, row, lane, g_scal[1]);
        float z = expf(g_log2[row] - g_scal[2]) * g_scal[3];
        float xs[8];
        ld_h8(g_x1h + (size_t)row * 256 + lane * 8, xs);
#pragma unroll
        for (int i = 0; i < 8; i++) e[i] = xs[i] + z * (acc[i] - xs[i]);
        float* orow = out_xenc + (size_t)row * 256 + lane * 8;
        *(float4*)orow       = make_float4(e[0], e[1], e[2], e[3]);
        *(float4*)(orow + 4) = make_float4(e[4], e[5], e[6], e[7]);
    }
#pragma unroll
    for (int i = 0; i < 8; i++) sm[warp][lane * 8 + i] = e[i];
    __syncthreads();

    int col = threadIdx.x;
    float s = 0.f;
#pragma unroll
    for (int w = 0; w < 8; w++) s += sm[w][col];
    atomicAdd(&g_meanp[blockIdx.x & (NMP - 1)][col], s);
}

// ---------------------------------------------------------------------------
// Softmax stats over N logits for both gates (single block).
// ---------------------------------------------------------------------------
__global__ __launch_bounds__(1024) void k_softmax_stats(int n)
{
    __shared__ float s1[32], s2[32];
    int tid = threadIdx.x;
    int lane = tid & 31, wp = tid >> 5;

    float m1 = -3.0e38f, m2 = -3.0e38f;
    for (int i = tid; i < n; i += 1024) {
        m1 = fmaxf(m1, g_log1[i]);
        m2 = fmaxf(m2, g_log2[i]);
    }
    for (int o = 16; o; o >>= 1) {
        m1 = fmaxf(m1, __shfl_xor_sync(0xffffffffu, m1, o));
        m2 = fmaxf(m2, __shfl_xor_sync(0xffffffffu, m2, o));
    }
    if (lane == 0) { s1[wp] = m1; s2[wp] = m2; }
    __syncthreads();
    if (tid < 32) {
        m1 = s1[tid]; m2 = s2[tid];
        for (int o = 16; o; o >>= 1) {
            m1 = fmaxf(m1, __shfl_xor_sync(0xffffffffu, m1, o));
            m2 = fmaxf(m2, __shfl_xor_sync(0xffffffffu, m2, o));
        }
        if (tid == 0) { s1[0] = m1; s2[0] = m2; }
    }
    __syncthreads();
    float M1 = s1[0], M2 = s2[0];
    __syncthreads();

    float a1 = 0.f, a2 = 0.f;
    for (int i = tid; i < n; i += 1024) {
        a1 += expf(g_log1[i] - M1);
        a2 += expf(g_log2[i] - M2);
    }
    for (int o = 16; o; o >>= 1) {
        a1 += __shfl_xor_sync(0xffffffffu, a1, o);
        a2 += __shfl_xor_sync(0xffffffffu, a2, o);
    }
    if (lane == 0) { s1[wp] = a1; s2[wp] = a2; }
    __syncthreads();
    if (tid == 0) {
        float t1 = 0.f, t2 = 0.f;
        for (int w = 0; w < 32; w++) { t1 += s1[w]; t2 += s2[w]; }
        g_scal[0] = M1; g_scal[1] = 1.0f / t1;
        g_scal[2] = M2; g_scal[3] = 1.0f / t2;
    }
}

// out = (colsum/N) @ e2p_w + e2p_b  (single block, 256 threads)
__global__ __launch_bounds__(256) void k_head(
    const float* __restrict__ w, const float* __restrict__ b,
    float* __restrict__ out, int n)
{
    __shared__ float mean[HID];
    int t = threadIdx.x;
    float s = 0.f;
#pragma unroll
    for (int p = 0; p < NMP; p++) s += g_meanp[p][t];
    mean[t] = s;
    __syncthreads();
    if (t < NOUT) {
        float invn = 1.0f / (float)n;
        float o = 0.f;
        for (int k = 0; k < HID; k++) o += mean[k] * w[k * NOUT + t];
        out[t] = o * invn + b[t];
    }
}

// ---------------------------------------------------------------------------
extern "C" void kernel_launch(void* const* d_in, const int* in_sizes, int n_in,
                              void* d_out, int out_size)
{
    const float* inputs = (const float*)d_in[0];
    const int*   erow   = (const int*)d_in[1];
    const int*   ecol   = (const int*)d_in[2];
    const float* evalv  = (const float*)d_in[3];
    const float* Wself1 = (const float*)d_in[4];
    const float* Wnb1   = (const float*)d_in[5];
    const float* b1     = (const float*)d_in[6];
    const float* Wself2 = (const float*)d_in[7];
    const float* Wnb2   = (const float*)d_in[8];
    const float* b2     = (const float*)d_in[9];
    const float* g1w    = (const float*)d_in[10];
    const float* g1b    = (const float*)d_in[11];
    const float* g2w    = (const float*)d_in[12];
    const float* g2b    = (const float*)d_in[13];
    const float* e2pw   = (const float*)d_in[14];
    const float* e2pb   = (const float*)d_in[15];

    int N = in_sizes[0] / HID;
    int E = in_sizes[1];
    float* out = (float*)d_out;

    dim3 ggrid(4, (N + 127) / 128);             // slice-major: A-tile L2 reuse
    int eb4 = (E + 1023) / 1024;
    int gb = (N + 7) / 8;
    int n4 = (N * HID) / 4;
    int xb = (n4 + 255) / 256;
    int zb = (N + 255) / 256;                   // >= (NMP*HID)/256 = 64
    int sb = (N + SCB - 1) / SCB;

    // Prep (converts + zeroing) + CSR build (shared by both layers)
    k_prep<<<xb + 256 + zb, 256>>>(inputs, Wself1, Wnb1, Wself2, Wnb2, n4, xb, N);
    k_count<<<eb4, 256>>>(erow, E);
    k_scan1<<<sb, SCB>>>(N);
    k_scan2<<<1, 32>>>(sb, N, E);
    k_scan3<<<sb, SCB>>>(N);
    k_fill<<<eb4, 256>>>(erow, ecol, evalv, E);

    // Layer 1
    k_gemm_dual<<<ggrid, 256>>>(b1, N, 0);
    k_gather_l1<<<gb, 256>>>(g1w, g1b, g2w, g2b, N);
    k_softmax_stats<<<1, 1024>>>(N);

    // Layer 2 (row gate r folded into GEMM epilogue; invsum folded into gather)
    k_gemm_dual<<<ggrid, 256>>>(b2, N, 1);
    k_gather_l2<<<gb, 256>>>(out, N);

    // Head
    k_head<<<1, 256>>>(e2pw, e2pb, out + (size_t)N * HID, N);
}